// round 1
// baseline (speedup 1.0000x reference)
#include <cuda_runtime.h>

#define NN 50000
#define DD 128
#define EE 600000
#define PP 100000

// ---- scratch (static device allocations; no runtime alloc) ----
__device__ float g_hA[NN * DD];
__device__ float g_hB[NN * DD];
__device__ float g_agg[NN * DD];
__device__ float g_invdeg[NN];

// ---------------------------------------------------------------
// degree kernels
// ---------------------------------------------------------------
__global__ void deg_count_kernel(const int* __restrict__ dst, float* __restrict__ deg) {
    int i = blockIdx.x * blockDim.x + threadIdx.x;
    if (i < EE) atomicAdd(&deg[dst[i]], 1.0f);
}

__global__ void deg_inv_kernel(float* __restrict__ deg) {
    int i = blockIdx.x * blockDim.x + threadIdx.x;
    if (i < NN) deg[i] = 1.0f / fmaxf(deg[i], 1.0f);
}

// ---------------------------------------------------------------
// scatter: agg[dst] += h[src]   (one warp-slice of 32 threads per edge,
// each thread handles 4 contiguous floats via float4 load + 4 atomics)
// ---------------------------------------------------------------
__global__ void scatter_kernel(const float* __restrict__ h,
                               const int* __restrict__ src,
                               const int* __restrict__ dst,
                               float* __restrict__ agg) {
    int idx = blockIdx.x * blockDim.x + threadIdx.x;
    int e = idx >> 5;
    int lane = idx & 31;
    if (e >= EE) return;
    int s = src[e];
    int d = dst[e];
    float4 v = ((const float4*)(h + (size_t)s * DD))[lane];
    float* a = agg + (size_t)d * DD + lane * 4;
    atomicAdd(a + 0, v.x);
    atomicAdd(a + 1, v.y);
    atomicAdd(a + 2, v.z);
    atomicAdd(a + 3, v.w);
}

// ---------------------------------------------------------------
// fused SAGE layer: out = act( h @ Wself + (agg * invdeg) @ Wneigh + b )
// block = 256 threads, tile = 64 rows x 128 cols, thread tile 8x4
// ---------------------------------------------------------------
__global__ void __launch_bounds__(256) sage_layer_kernel(
    const float* __restrict__ A,       // h_in  [NN, DD]
    const float* __restrict__ G,       // agg   [NN, DD]
    const float* __restrict__ invdeg,  // [NN]
    const float* __restrict__ Wself,   // [DD, DD]
    const float* __restrict__ Wneigh,  // [DD, DD]
    const float* __restrict__ bias,    // [DD]
    float* __restrict__ out,           // [NN, DD]
    int do_relu)
{
    __shared__ float As[32][68];   // [k][row], padded (68*4B = multiple of 16B)
    __shared__ float Ws[32][DD];   // [k][col]

    int tid = threadIdx.x;
    int tx = tid & 31;       // col group: cols tx*4 .. tx*4+3
    int ty = tid >> 5;       // row group: rows ty*8 .. ty*8+7
    int row0 = blockIdx.x * 64;

    float acc[8][4];
#pragma unroll
    for (int i = 0; i < 8; i++)
#pragma unroll
        for (int j = 0; j < 4; j++) acc[i][j] = 0.f;

    for (int phase = 0; phase < 2; phase++) {
        const float* Ap = phase ? G : A;
        const float* Wp = phase ? Wneigh : Wself;
        for (int k0 = 0; k0 < DD; k0 += 32) {
            // load A tile (64 rows x 32 k), transposed into As[k][row]
#pragma unroll
            for (int i = 0; i < 2; i++) {
                int f = tid * 2 + i;         // 0..511 float4 slots
                int r = f >> 3;              // 0..63
                int kq = f & 7;              // 0..7 (k = kq*4)
                int row = row0 + r;
                int rc = row < NN ? row : NN - 1;
                float4 v = *(const float4*)(Ap + (size_t)rc * DD + k0 + kq * 4);
                if (phase) {
                    float sc = invdeg[rc];
                    v.x *= sc; v.y *= sc; v.z *= sc; v.w *= sc;
                }
                As[kq * 4 + 0][r] = v.x;
                As[kq * 4 + 1][r] = v.y;
                As[kq * 4 + 2][r] = v.z;
                As[kq * 4 + 3][r] = v.w;
            }
            // load W tile (32 k x 128 cols)
#pragma unroll
            for (int i = 0; i < 4; i++) {
                int f = tid + i * 256;       // 0..1023 float4 slots
                int k = f >> 5;              // 0..31
                int c4 = f & 31;
                *(float4*)&Ws[k][c4 * 4] =
                    *(const float4*)(Wp + (size_t)(k0 + k) * DD + c4 * 4);
            }
            __syncthreads();
#pragma unroll
            for (int k = 0; k < 32; k++) {
                float4 a0 = *(float4*)&As[k][ty * 8];
                float4 a1 = *(float4*)&As[k][ty * 8 + 4];
                float4 w  = *(float4*)&Ws[k][tx * 4];
                float ar[8] = {a0.x, a0.y, a0.z, a0.w, a1.x, a1.y, a1.z, a1.w};
#pragma unroll
                for (int i = 0; i < 8; i++) {
                    acc[i][0] += ar[i] * w.x;
                    acc[i][1] += ar[i] * w.y;
                    acc[i][2] += ar[i] * w.z;
                    acc[i][3] += ar[i] * w.w;
                }
            }
            __syncthreads();
        }
    }

    int c0 = tx * 4;
    float4 bv = *(const float4*)(bias + c0);
    float br[4] = {bv.x, bv.y, bv.z, bv.w};
#pragma unroll
    for (int i = 0; i < 8; i++) {
        int row = row0 + ty * 8 + i;
        if (row < NN) {
            float v0 = acc[i][0] + br[0];
            float v1 = acc[i][1] + br[1];
            float v2 = acc[i][2] + br[2];
            float v3 = acc[i][3] + br[3];
            if (do_relu) {
                v0 = fmaxf(v0, 0.f); v1 = fmaxf(v1, 0.f);
                v2 = fmaxf(v2, 0.f); v3 = fmaxf(v3, 0.f);
            }
            float4 o = {v0, v1, v2, v3};
            *(float4*)(out + (size_t)row * DD + c0) = o;
        }
    }
}

// ---------------------------------------------------------------
// predictor: for each pair, e = h[s]*h[d]; t1 = relu(e@Wp1+bp1);
// t2 = relu(t1@Wp2+bp2); out = t2@Wp3 + bp3.
// block = 256 threads, 64 pairs per block.
// ---------------------------------------------------------------
__global__ void __launch_bounds__(256) predictor_kernel(
    const float* __restrict__ h,
    const int* __restrict__ pos_src, const int* __restrict__ pos_dst,
    const int* __restrict__ neg_src, const int* __restrict__ neg_dst,
    const float* __restrict__ Wp1, const float* __restrict__ bp1,
    const float* __restrict__ Wp2, const float* __restrict__ bp2,
    const float* __restrict__ Wp3, const float* __restrict__ bp3,
    float* __restrict__ out)
{
    __shared__ float Es[DD][64];   // [k][pair]  (also reused for t1)  32KB
    __shared__ float Ws[32][DD];   // 16KB  -> total 48KB exactly

    int tid = threadIdx.x;
    int tx = tid & 31;
    int ty = tid >> 5;
    int g0 = blockIdx.x * 64;

    // ---- stage 1: e = h[src]*h[dst], stored transposed ----
    {
        int p = tid >> 2;        // 0..63 local pair
        int seg = tid & 3;       // k segment: seg*32 .. seg*32+31
        int g = g0 + p;
        int s, d;
        if (g < PP) { s = pos_src[g]; d = pos_dst[g]; }
        else        { s = neg_src[g - PP]; d = neg_dst[g - PP]; }
        const float4* hs = (const float4*)(h + (size_t)s * DD + seg * 32);
        const float4* hd = (const float4*)(h + (size_t)d * DD + seg * 32);
#pragma unroll
        for (int i = 0; i < 8; i++) {
            float4 a = hs[i];
            float4 bb = hd[i];
            int k = seg * 32 + i * 4;
            Es[k + 0][p] = a.x * bb.x;
            Es[k + 1][p] = a.y * bb.y;
            Es[k + 2][p] = a.z * bb.z;
            Es[k + 3][p] = a.w * bb.w;
        }
    }
    __syncthreads();

    float acc[8][4];

    // ---- GEMM 1: t1 = e @ Wp1 ----
#pragma unroll
    for (int i = 0; i < 8; i++)
#pragma unroll
        for (int j = 0; j < 4; j++) acc[i][j] = 0.f;

    for (int k0 = 0; k0 < DD; k0 += 32) {
#pragma unroll
        for (int i = 0; i < 4; i++) {
            int f = tid + i * 256;
            int k = f >> 5, c4 = f & 31;
            *(float4*)&Ws[k][c4 * 4] =
                *(const float4*)(Wp1 + (size_t)(k0 + k) * DD + c4 * 4);
        }
        __syncthreads();
#pragma unroll
        for (int k = 0; k < 32; k++) {
            float4 a0 = *(float4*)&Es[k0 + k][ty * 8];
            float4 a1 = *(float4*)&Es[k0 + k][ty * 8 + 4];
            float4 w  = *(float4*)&Ws[k][tx * 4];
            float ar[8] = {a0.x, a0.y, a0.z, a0.w, a1.x, a1.y, a1.z, a1.w};
#pragma unroll
            for (int i = 0; i < 8; i++) {
                acc[i][0] += ar[i] * w.x;
                acc[i][1] += ar[i] * w.y;
                acc[i][2] += ar[i] * w.z;
                acc[i][3] += ar[i] * w.w;
            }
        }
        __syncthreads();
    }

    // ---- t1 = relu(acc + bp1), write back transposed into Es ----
    {
        float4 bv = *(const float4*)(bp1 + tx * 4);
        float br[4] = {bv.x, bv.y, bv.z, bv.w};
#pragma unroll
        for (int i = 0; i < 8; i++)
#pragma unroll
            for (int j = 0; j < 4; j++)
                Es[tx * 4 + j][ty * 8 + i] = fmaxf(acc[i][j] + br[j], 0.f);
    }
    __syncthreads();

    // ---- GEMM 2: t2 = t1 @ Wp2 ----
#pragma unroll
    for (int i = 0; i < 8; i++)
#pragma unroll
        for (int j = 0; j < 4; j++) acc[i][j] = 0.f;

    for (int k0 = 0; k0 < DD; k0 += 32) {
#pragma unroll
        for (int i = 0; i < 4; i++) {
            int f = tid + i * 256;
            int k = f >> 5, c4 = f & 31;
            *(float4*)&Ws[k][c4 * 4] =
                *(const float4*)(Wp2 + (size_t)(k0 + k) * DD + c4 * 4);
        }
        __syncthreads();
#pragma unroll
        for (int k = 0; k < 32; k++) {
            float4 a0 = *(float4*)&Es[k0 + k][ty * 8];
            float4 a1 = *(float4*)&Es[k0 + k][ty * 8 + 4];
            float4 w  = *(float4*)&Ws[k][tx * 4];
            float ar[8] = {a0.x, a0.y, a0.z, a0.w, a1.x, a1.y, a1.z, a1.w};
#pragma unroll
            for (int i = 0; i < 8; i++) {
                acc[i][0] += ar[i] * w.x;
                acc[i][1] += ar[i] * w.y;
                acc[i][2] += ar[i] * w.z;
                acc[i][3] += ar[i] * w.w;
            }
        }
        __syncthreads();
    }

    // ---- t2 = relu(acc + bp2); score = t2 . Wp3 + bp3 ----
    float4 w3 = *(const float4*)(Wp3 + tx * 4);
    float4 b2 = *(const float4*)(bp2 + tx * 4);
    float part[8];
#pragma unroll
    for (int i = 0; i < 8; i++) {
        float t0 = fmaxf(acc[i][0] + b2.x, 0.f);
        float t1 = fmaxf(acc[i][1] + b2.y, 0.f);
        float t2 = fmaxf(acc[i][2] + b2.z, 0.f);
        float t3 = fmaxf(acc[i][3] + b2.w, 0.f);
        part[i] = t0 * w3.x + t1 * w3.y + t2 * w3.z + t3 * w3.w;
    }
#pragma unroll
    for (int off = 16; off; off >>= 1)
#pragma unroll
        for (int i = 0; i < 8; i++)
            part[i] += __shfl_xor_sync(0xffffffffu, part[i], off);

    if (tx == 0) {
        float b3 = bp3[0];
#pragma unroll
        for (int i = 0; i < 8; i++)
            out[g0 + ty * 8 + i] = part[i] + b3;
    }
}

// ---------------------------------------------------------------
// launch
// ---------------------------------------------------------------
extern "C" void kernel_launch(void* const* d_in, const int* in_sizes, int n_in,
                              void* d_out, int out_size) {
    const float* x       = (const float*)d_in[0];
    const float* W_self  = (const float*)d_in[1];
    const float* W_neigh = (const float*)d_in[2];
    const float* b       = (const float*)d_in[3];
    const float* Wp1     = (const float*)d_in[4];
    const float* bp1     = (const float*)d_in[5];
    const float* Wp2     = (const float*)d_in[6];
    const float* bp2     = (const float*)d_in[7];
    const float* Wp3     = (const float*)d_in[8];
    const float* bp3     = (const float*)d_in[9];
    const int* edge_src  = (const int*)d_in[10];
    const int* edge_dst  = (const int*)d_in[11];
    const int* pos_src   = (const int*)d_in[12];
    const int* pos_dst   = (const int*)d_in[13];
    const int* neg_src   = (const int*)d_in[14];
    const int* neg_dst   = (const int*)d_in[15];
    float* out = (float*)d_out;

    float *hA, *hB, *agg, *invdeg;
    cudaGetSymbolAddress((void**)&hA, g_hA);
    cudaGetSymbolAddress((void**)&hB, g_hB);
    cudaGetSymbolAddress((void**)&agg, g_agg);
    cudaGetSymbolAddress((void**)&invdeg, g_invdeg);

    // degree
    cudaMemsetAsync(invdeg, 0, NN * sizeof(float));
    deg_count_kernel<<<(EE + 255) / 256, 256>>>(edge_dst, invdeg);
    deg_inv_kernel<<<(NN + 255) / 256, 256>>>(invdeg);

    // layers
    const float* hin = x;
    float* outs[3] = {hA, hB, hA};
    for (int l = 0; l < 3; l++) {
        cudaMemsetAsync(agg, 0, (size_t)NN * DD * sizeof(float));
        scatter_kernel<<<(EE * 32 + 255) / 256, 256>>>(hin, edge_src, edge_dst, agg);
        sage_layer_kernel<<<(NN + 63) / 64, 256>>>(
            hin, agg, invdeg,
            W_self + (size_t)l * DD * DD,
            W_neigh + (size_t)l * DD * DD,
            b + (size_t)l * DD,
            outs[l], (l < 2) ? 1 : 0);
        hin = outs[l];
    }

    // predictor (pos pairs occupy out[0..P), neg out[P..2P))
    predictor_kernel<<<(2 * PP) / 64, 256>>>(
        hin, pos_src, pos_dst, neg_src, neg_dst,
        Wp1, bp1, Wp2, bp2, Wp3, bp3, out);
}

// round 2
// speedup vs baseline: 1.5098x; 1.5098x over previous
#include <cuda_runtime.h>

#define NN 50000
#define DD 128
#define EE 600000
#define PP 100000

// packed f32x2 helpers
#define FMA2(acc, a, b) \
    asm("fma.rn.f32x2 %0, %1, %2, %0;" : "+l"(acc) : "l"(a), "l"(b))
#define DUP2(d, s) \
    asm("mov.b64 %0, {%1, %1};" : "=l"(d) : "f"(s))
#define UNPK2(lo, hi, v) \
    asm("mov.b64 {%0, %1}, %2;" : "=f"(lo), "=f"(hi) : "l"(v))

// ---- scratch (static device allocations; no runtime alloc) ----
__device__ float g_hA[NN * DD];
__device__ float g_hB[NN * DD];
__device__ float g_agg[NN * DD];
__device__ float g_invdeg[NN];

// ---------------------------------------------------------------
// degree kernels
// ---------------------------------------------------------------
__global__ void deg_count_kernel(const int* __restrict__ dst, float* __restrict__ deg) {
    int i = blockIdx.x * blockDim.x + threadIdx.x;
    if (i < EE) atomicAdd(&deg[dst[i]], 1.0f);
}

__global__ void deg_inv_kernel(float* __restrict__ deg) {
    int i = blockIdx.x * blockDim.x + threadIdx.x;
    if (i < NN) deg[i] = 1.0f / fmaxf(deg[i], 1.0f);
}

// ---------------------------------------------------------------
// scatter: agg[dst] += h[src]  — one warp per edge, each lane does one
// 16B vector reduction (red.global.add.v4.f32, sm_90+)
// ---------------------------------------------------------------
__global__ void scatter_kernel(const float* __restrict__ h,
                               const int* __restrict__ src,
                               const int* __restrict__ dst,
                               float* __restrict__ agg) {
    int idx = blockIdx.x * blockDim.x + threadIdx.x;
    int e = idx >> 5;
    int lane = idx & 31;
    if (e >= EE) return;
    int s = src[e];
    int d = dst[e];
    float4 v = __ldg((const float4*)(h + (size_t)s * DD) + lane);
    float* a = agg + (size_t)d * DD + lane * 4;
    asm volatile("red.global.add.v4.f32 [%0], {%1, %2, %3, %4};"
                 :: "l"(a), "f"(v.x), "f"(v.y), "f"(v.z), "f"(v.w)
                 : "memory");
}

// ---------------------------------------------------------------
// fused SAGE layer: out = act( h @ Wself + (agg * invdeg) @ Wneigh + b )
// 256 threads, tile 64 rows x 128 cols, thread tile 8x4, FFMA2 inner loop
// ---------------------------------------------------------------
__global__ void __launch_bounds__(256) sage_layer_kernel(
    const float* __restrict__ A,       // h_in  [NN, DD]
    const float* __restrict__ G,       // agg   [NN, DD]
    const float* __restrict__ invdeg,  // [NN]
    const float* __restrict__ Wself,   // [DD, DD]
    const float* __restrict__ Wneigh,  // [DD, DD]
    const float* __restrict__ bias,    // [DD]
    float* __restrict__ out,           // [NN, DD]
    int do_relu)
{
    __shared__ float As[32][68];   // [k][row]
    __shared__ float Ws[32][DD];   // [k][col]

    int tid = threadIdx.x;
    int tx = tid & 31;       // cols tx*4 .. tx*4+3
    int ty = tid >> 5;       // rows ty*8 .. ty*8+7
    int row0 = blockIdx.x * 64;

    unsigned long long acc2[4][4];   // [row-pair][col], each = 2 rows packed
#pragma unroll
    for (int p = 0; p < 4; p++)
#pragma unroll
        for (int j = 0; j < 4; j++) acc2[p][j] = 0ull;

    for (int phase = 0; phase < 2; phase++) {
        const float* Ap = phase ? G : A;
        const float* Wp = phase ? Wneigh : Wself;
        for (int k0 = 0; k0 < DD; k0 += 32) {
            // load A tile (64 rows x 32 k), transposed into As[k][row]
#pragma unroll
            for (int i = 0; i < 2; i++) {
                int f = tid * 2 + i;         // 0..511 float4 slots
                int r = f >> 3;              // 0..63
                int kq = f & 7;              // k = kq*4
                int row = row0 + r;
                int rc = row < NN ? row : NN - 1;
                float4 v = *(const float4*)(Ap + (size_t)rc * DD + k0 + kq * 4);
                if (phase) {
                    float sc = invdeg[rc];
                    v.x *= sc; v.y *= sc; v.z *= sc; v.w *= sc;
                }
                As[kq * 4 + 0][r] = v.x;
                As[kq * 4 + 1][r] = v.y;
                As[kq * 4 + 2][r] = v.z;
                As[kq * 4 + 3][r] = v.w;
            }
            // load W tile (32 k x 128 cols)
#pragma unroll
            for (int i = 0; i < 4; i++) {
                int f = tid + i * 256;       // 0..1023 float4 slots
                int k = f >> 5;
                int c4 = f & 31;
                *(float4*)&Ws[k][c4 * 4] =
                    *(const float4*)(Wp + (size_t)(k0 + k) * DD + c4 * 4);
            }
            __syncthreads();
#pragma unroll 8
            for (int k = 0; k < 32; k++) {
                ulonglong2 a01 = *(const ulonglong2*)&As[k][ty * 8];
                ulonglong2 a23 = *(const ulonglong2*)&As[k][ty * 8 + 4];
                float4 w = *(const float4*)&Ws[k][tx * 4];
                unsigned long long wd0, wd1, wd2, wd3;
                DUP2(wd0, w.x); DUP2(wd1, w.y); DUP2(wd2, w.z); DUP2(wd3, w.w);
                FMA2(acc2[0][0], a01.x, wd0); FMA2(acc2[0][1], a01.x, wd1);
                FMA2(acc2[0][2], a01.x, wd2); FMA2(acc2[0][3], a01.x, wd3);
                FMA2(acc2[1][0], a01.y, wd0); FMA2(acc2[1][1], a01.y, wd1);
                FMA2(acc2[1][2], a01.y, wd2); FMA2(acc2[1][3], a01.y, wd3);
                FMA2(acc2[2][0], a23.x, wd0); FMA2(acc2[2][1], a23.x, wd1);
                FMA2(acc2[2][2], a23.x, wd2); FMA2(acc2[2][3], a23.x, wd3);
                FMA2(acc2[3][0], a23.y, wd0); FMA2(acc2[3][1], a23.y, wd1);
                FMA2(acc2[3][2], a23.y, wd2); FMA2(acc2[3][3], a23.y, wd3);
            }
            __syncthreads();
        }
    }

    int c0 = tx * 4;
    float4 bv = *(const float4*)(bias + c0);
#pragma unroll
    for (int p = 0; p < 4; p++) {
        float lo[4], hi[4];
#pragma unroll
        for (int j = 0; j < 4; j++) UNPK2(lo[j], hi[j], acc2[p][j]);
        float4 vlo = {lo[0] + bv.x, lo[1] + bv.y, lo[2] + bv.z, lo[3] + bv.w};
        float4 vhi = {hi[0] + bv.x, hi[1] + bv.y, hi[2] + bv.z, hi[3] + bv.w};
        if (do_relu) {
            vlo.x = fmaxf(vlo.x, 0.f); vlo.y = fmaxf(vlo.y, 0.f);
            vlo.z = fmaxf(vlo.z, 0.f); vlo.w = fmaxf(vlo.w, 0.f);
            vhi.x = fmaxf(vhi.x, 0.f); vhi.y = fmaxf(vhi.y, 0.f);
            vhi.z = fmaxf(vhi.z, 0.f); vhi.w = fmaxf(vhi.w, 0.f);
        }
        int r = row0 + ty * 8 + 2 * p;
        if (r < NN)     *(float4*)(out + (size_t)r * DD + c0) = vlo;
        if (r + 1 < NN) *(float4*)(out + (size_t)(r + 1) * DD + c0) = vhi;
    }
}

// ---------------------------------------------------------------
// predictor: e = h[s]*h[d]; t1 = relu(e@Wp1+bp1); t2 = relu(t1@Wp2+bp2);
// out = t2@Wp3 + bp3.  64 pairs/block, 256 threads, W resident in smem.
// dynamic smem: Wb[128][128] (64KB) + Es[128][68] (34KB)
// ---------------------------------------------------------------
__global__ void __launch_bounds__(256) predictor_kernel(
    const float* __restrict__ h,
    const int* __restrict__ pos_src, const int* __restrict__ pos_dst,
    const int* __restrict__ neg_src, const int* __restrict__ neg_dst,
    const float* __restrict__ Wp1, const float* __restrict__ bp1,
    const float* __restrict__ Wp2, const float* __restrict__ bp2,
    const float* __restrict__ Wp3, const float* __restrict__ bp3,
    float* __restrict__ out)
{
    extern __shared__ float psmem[];
    float (*Wb)[DD] = (float(*)[DD])psmem;                 // [128][128]
    float (*Es)[68] = (float(*)[68])(psmem + DD * DD);     // [128][68]

    int tid = threadIdx.x;
    int tx = tid & 31;
    int ty = tid >> 5;
    int g0 = blockIdx.x * 64;

    // ---- stage 1: e = h[src]*h[dst], stored transposed Es[k][pair] ----
    {
        int p = tid >> 2;        // 0..63 local pair
        int seg = tid & 3;       // k segment
        int g = g0 + p;
        int s, d;
        if (g < PP) { s = pos_src[g]; d = pos_dst[g]; }
        else        { s = neg_src[g - PP]; d = neg_dst[g - PP]; }
        const float4* hs = (const float4*)(h + (size_t)s * DD + seg * 32);
        const float4* hd = (const float4*)(h + (size_t)d * DD + seg * 32);
#pragma unroll
        for (int i = 0; i < 8; i++) {
            float4 a = hs[i];
            float4 bb = hd[i];
            int k = seg * 32 + i * 4;
            Es[k + 0][p] = a.x * bb.x;
            Es[k + 1][p] = a.y * bb.y;
            Es[k + 2][p] = a.z * bb.z;
            Es[k + 3][p] = a.w * bb.w;
        }
    }
    // ---- load W1 fully ----
#pragma unroll
    for (int i = 0; i < 16; i++) {
        int f = tid + i * 256;       // 0..4095 float4 slots
        int k = f >> 5;
        int c4 = f & 31;
        *(float4*)&Wb[k][c4 * 4] = *(const float4*)(Wp1 + (size_t)k * DD + c4 * 4);
    }
    __syncthreads();

    unsigned long long acc2[4][4];

    // ---- GEMM 1 ----
#pragma unroll
    for (int p = 0; p < 4; p++)
#pragma unroll
        for (int j = 0; j < 4; j++) acc2[p][j] = 0ull;
#pragma unroll 8
    for (int k = 0; k < DD; k++) {
        ulonglong2 a01 = *(const ulonglong2*)&Es[k][ty * 8];
        ulonglong2 a23 = *(const ulonglong2*)&Es[k][ty * 8 + 4];
        float4 w = *(const float4*)&Wb[k][tx * 4];
        unsigned long long wd0, wd1, wd2, wd3;
        DUP2(wd0, w.x); DUP2(wd1, w.y); DUP2(wd2, w.z); DUP2(wd3, w.w);
        FMA2(acc2[0][0], a01.x, wd0); FMA2(acc2[0][1], a01.x, wd1);
        FMA2(acc2[0][2], a01.x, wd2); FMA2(acc2[0][3], a01.x, wd3);
        FMA2(acc2[1][0], a01.y, wd0); FMA2(acc2[1][1], a01.y, wd1);
        FMA2(acc2[1][2], a01.y, wd2); FMA2(acc2[1][3], a01.y, wd3);
        FMA2(acc2[2][0], a23.x, wd0); FMA2(acc2[2][1], a23.x, wd1);
        FMA2(acc2[2][2], a23.x, wd2); FMA2(acc2[2][3], a23.x, wd3);
        FMA2(acc2[3][0], a23.y, wd0); FMA2(acc2[3][1], a23.y, wd1);
        FMA2(acc2[3][2], a23.y, wd2); FMA2(acc2[3][3], a23.y, wd3);
    }
    __syncthreads();   // all Es reads + Wb reads of GEMM1 done

    // ---- t1 = relu(acc + bp1) written transposed back to Es;
    //      simultaneously reload Wb with Wp2 ----
    {
        float4 bv = *(const float4*)(bp1 + tx * 4);
        float br[4] = {bv.x, bv.y, bv.z, bv.w};
#pragma unroll
        for (int p = 0; p < 4; p++) {
            float lo[4], hi[4];
#pragma unroll
            for (int j = 0; j < 4; j++) UNPK2(lo[j], hi[j], acc2[p][j]);
#pragma unroll
            for (int j = 0; j < 4; j++) {
                Es[tx * 4 + j][ty * 8 + 2 * p]     = fmaxf(lo[j] + br[j], 0.f);
                Es[tx * 4 + j][ty * 8 + 2 * p + 1] = fmaxf(hi[j] + br[j], 0.f);
            }
        }
#pragma unroll
        for (int i = 0; i < 16; i++) {
            int f = tid + i * 256;
            int k = f >> 5;
            int c4 = f & 31;
            *(float4*)&Wb[k][c4 * 4] = *(const float4*)(Wp2 + (size_t)k * DD + c4 * 4);
        }
    }
    __syncthreads();

    // ---- GEMM 2 ----
#pragma unroll
    for (int p = 0; p < 4; p++)
#pragma unroll
        for (int j = 0; j < 4; j++) acc2[p][j] = 0ull;
#pragma unroll 8
    for (int k = 0; k < DD; k++) {
        ulonglong2 a01 = *(const ulonglong2*)&Es[k][ty * 8];
        ulonglong2 a23 = *(const ulonglong2*)&Es[k][ty * 8 + 4];
        float4 w = *(const float4*)&Wb[k][tx * 4];
        unsigned long long wd0, wd1, wd2, wd3;
        DUP2(wd0, w.x); DUP2(wd1, w.y); DUP2(wd2, w.z); DUP2(wd3, w.w);
        FMA2(acc2[0][0], a01.x, wd0); FMA2(acc2[0][1], a01.x, wd1);
        FMA2(acc2[0][2], a01.x, wd2); FMA2(acc2[0][3], a01.x, wd3);
        FMA2(acc2[1][0], a01.y, wd0); FMA2(acc2[1][1], a01.y, wd1);
        FMA2(acc2[1][2], a01.y, wd2); FMA2(acc2[1][3], a01.y, wd3);
        FMA2(acc2[2][0], a23.x, wd0); FMA2(acc2[2][1], a23.x, wd1);
        FMA2(acc2[2][2], a23.x, wd2); FMA2(acc2[2][3], a23.x, wd3);
        FMA2(acc2[3][0], a23.y, wd0); FMA2(acc2[3][1], a23.y, wd1);
        FMA2(acc2[3][2], a23.y, wd2); FMA2(acc2[3][3], a23.y, wd3);
    }

    // ---- t2 = relu(acc + bp2); score = t2 . Wp3 + bp3 ----
    float4 w3 = *(const float4*)(Wp3 + tx * 4);
    float4 b2 = *(const float4*)(bp2 + tx * 4);
    float part[8];
#pragma unroll
    for (int p = 0; p < 4; p++) {
        float lo[4], hi[4];
#pragma unroll
        for (int j = 0; j < 4; j++) UNPK2(lo[j], hi[j], acc2[p][j]);
        float t0 = fmaxf(lo[0] + b2.x, 0.f), t1 = fmaxf(lo[1] + b2.y, 0.f);
        float t2 = fmaxf(lo[2] + b2.z, 0.f), t3 = fmaxf(lo[3] + b2.w, 0.f);
        part[2 * p] = t0 * w3.x + t1 * w3.y + t2 * w3.z + t3 * w3.w;
        t0 = fmaxf(hi[0] + b2.x, 0.f); t1 = fmaxf(hi[1] + b2.y, 0.f);
        t2 = fmaxf(hi[2] + b2.z, 0.f); t3 = fmaxf(hi[3] + b2.w, 0.f);
        part[2 * p + 1] = t0 * w3.x + t1 * w3.y + t2 * w3.z + t3 * w3.w;
    }
#pragma unroll
    for (int off = 16; off; off >>= 1)
#pragma unroll
        for (int i = 0; i < 8; i++)
            part[i] += __shfl_xor_sync(0xffffffffu, part[i], off);

    if (tx == 0) {
        float b3 = bp3[0];
#pragma unroll
        for (int i = 0; i < 8; i++)
            out[g0 + ty * 8 + i] = part[i] + b3;
    }
}

// ---------------------------------------------------------------
// launch
// ---------------------------------------------------------------
extern "C" void kernel_launch(void* const* d_in, const int* in_sizes, int n_in,
                              void* d_out, int out_size) {
    const float* x       = (const float*)d_in[0];
    const float* W_self  = (const float*)d_in[1];
    const float* W_neigh = (const float*)d_in[2];
    const float* b       = (const float*)d_in[3];
    const float* Wp1     = (const float*)d_in[4];
    const float* bp1     = (const float*)d_in[5];
    const float* Wp2     = (const float*)d_in[6];
    const float* bp2     = (const float*)d_in[7];
    const float* Wp3     = (const float*)d_in[8];
    const float* bp3     = (const float*)d_in[9];
    const int* edge_src  = (const int*)d_in[10];
    const int* edge_dst  = (const int*)d_in[11];
    const int* pos_src   = (const int*)d_in[12];
    const int* pos_dst   = (const int*)d_in[13];
    const int* neg_src   = (const int*)d_in[14];
    const int* neg_dst   = (const int*)d_in[15];
    float* out = (float*)d_out;

    float *hA, *hB, *agg, *invdeg;
    cudaGetSymbolAddress((void**)&hA, g_hA);
    cudaGetSymbolAddress((void**)&hB, g_hB);
    cudaGetSymbolAddress((void**)&agg, g_agg);
    cudaGetSymbolAddress((void**)&invdeg, g_invdeg);

    static int attr_done = 0;
    const int PRED_SMEM = (DD * DD + DD * 68) * (int)sizeof(float);  // 100352
    if (!attr_done) {
        cudaFuncSetAttribute(predictor_kernel,
                             cudaFuncAttributeMaxDynamicSharedMemorySize, PRED_SMEM);
        attr_done = 1;
    }

    // degree
    cudaMemsetAsync(invdeg, 0, NN * sizeof(float));
    deg_count_kernel<<<(EE + 255) / 256, 256>>>(edge_dst, invdeg);
    deg_inv_kernel<<<(NN + 255) / 256, 256>>>(invdeg);

    // layers
    const float* hin = x;
    float* outs[3] = {hA, hB, hA};
    for (int l = 0; l < 3; l++) {
        cudaMemsetAsync(agg, 0, (size_t)NN * DD * sizeof(float));
        scatter_kernel<<<(EE * 32 + 255) / 256, 256>>>(hin, edge_src, edge_dst, agg);
        sage_layer_kernel<<<(NN + 63) / 64, 256>>>(
            hin, agg, invdeg,
            W_self + (size_t)l * DD * DD,
            W_neigh + (size_t)l * DD * DD,
            b + (size_t)l * DD,
            outs[l], (l < 2) ? 1 : 0);
        hin = outs[l];
    }

    // predictor (pos pairs occupy out[0..P), neg out[P..2P))
    predictor_kernel<<<(2 * PP) / 64, 256, PRED_SMEM>>>(
        hin, pos_src, pos_dst, neg_src, neg_dst,
        Wp1, bp1, Wp2, bp2, Wp3, bp3, out);
}

// round 3
// speedup vs baseline: 1.7280x; 1.1446x over previous
#include <cuda_runtime.h>

#define NN 50000
#define DD 128
#define EE 600000
#define PP 100000

// packed f32x2 helpers
#define FMA2(acc, a, b) \
    asm("fma.rn.f32x2 %0, %1, %2, %0;" : "+l"(acc) : "l"(a), "l"(b))
#define DUP2(d, s) \
    asm("mov.b64 %0, {%1, %1};" : "=l"(d) : "f"(s))
#define UNPK2(lo, hi, v) \
    asm("mov.b64 {%0, %1}, %2;" : "=f"(lo), "=f"(hi) : "l"(v))

// ---- scratch (static device allocations; no runtime alloc) ----
__device__ float g_hA[NN * DD];
__device__ float g_hB[NN * DD];
__device__ float g_agg[NN * DD];
__device__ float g_invdeg[NN];
__device__ int   g_deg[NN];
__device__ int   g_incl[NN];
__device__ int   g_bsum[64];
__device__ int   g_rows[NN + 1];
__device__ int   g_cursor[NN];
__device__ int   g_csr[EE];

// ---------------------------------------------------------------
// CSR build
// ---------------------------------------------------------------
__global__ void deg_count_kernel(const int* __restrict__ dst) {
    int i = blockIdx.x * blockDim.x + threadIdx.x;
    if (i < EE) atomicAdd(&g_deg[dst[i]], 1);
}

__global__ void scan1_kernel() {
    __shared__ int sh[1024];
    int b = blockIdx.x, t = threadIdx.x;
    int i = b * 1024 + t;
    int v = (i < NN) ? g_deg[i] : 0;
    sh[t] = v;
    __syncthreads();
#pragma unroll
    for (int off = 1; off < 1024; off <<= 1) {
        int x = (t >= off) ? sh[t - off] : 0;
        __syncthreads();
        sh[t] += x;
        __syncthreads();
    }
    if (i < NN) g_incl[i] = sh[t];
    if (t == 1023) g_bsum[b] = sh[1023];
}

__global__ void scan2_kernel(int nb) {
    if (threadIdx.x == 0) {
        int s = 0;
        for (int b = 0; b < nb; b++) { int v = g_bsum[b]; g_bsum[b] = s; s += v; }
    }
}

__global__ void scan3_kernel() {
    int i = blockIdx.x * blockDim.x + threadIdx.x;
    if (i < NN) {
        int excl = g_incl[i] - g_deg[i] + g_bsum[i >> 10];
        g_rows[i] = excl;
        g_cursor[i] = excl;
        g_invdeg[i] = 1.0f / (float)max(g_deg[i], 1);
    }
    if (i == 0) g_rows[NN] = EE;
}

__global__ void fill_kernel(const int* __restrict__ src, const int* __restrict__ dst) {
    int e = blockIdx.x * blockDim.x + threadIdx.x;
    if (e < EE) {
        int p = atomicAdd(&g_cursor[dst[e]], 1);
        g_csr[p] = src[e];
    }
}

// ---------------------------------------------------------------
// aggregate: agg[n] = invdeg[n] * sum_{e in CSR(n)} h[src_e]
// one warp per node, lane = one float4 of the row
// ---------------------------------------------------------------
__global__ void aggregate_kernel(const float* __restrict__ h, float* __restrict__ agg) {
    int w = (blockIdx.x * blockDim.x + threadIdx.x) >> 5;
    int lane = threadIdx.x & 31;
    if (w >= NN) return;
    int rs = g_rows[w], re = g_rows[w + 1];
    float4 acc = {0.f, 0.f, 0.f, 0.f};
    int i = rs;
    for (; i + 3 < re; i += 4) {
        int s0 = __ldg(&g_csr[i]);
        int s1 = __ldg(&g_csr[i + 1]);
        int s2 = __ldg(&g_csr[i + 2]);
        int s3 = __ldg(&g_csr[i + 3]);
        float4 a = __ldg((const float4*)(h + (size_t)s0 * DD) + lane);
        float4 b = __ldg((const float4*)(h + (size_t)s1 * DD) + lane);
        float4 c = __ldg((const float4*)(h + (size_t)s2 * DD) + lane);
        float4 d = __ldg((const float4*)(h + (size_t)s3 * DD) + lane);
        acc.x += a.x + b.x + c.x + d.x;
        acc.y += a.y + b.y + c.y + d.y;
        acc.z += a.z + b.z + c.z + d.z;
        acc.w += a.w + b.w + c.w + d.w;
    }
    for (; i < re; i++) {
        int s0 = __ldg(&g_csr[i]);
        float4 a = __ldg((const float4*)(h + (size_t)s0 * DD) + lane);
        acc.x += a.x; acc.y += a.y; acc.z += a.z; acc.w += a.w;
    }
    float sc = g_invdeg[w];
    acc.x *= sc; acc.y *= sc; acc.z *= sc; acc.w *= sc;
    ((float4*)(agg + (size_t)w * DD))[lane] = acc;
}

// ---------------------------------------------------------------
// fused SAGE layer: out = act( h @ Wself + agg @ Wneigh + b )
// 256 threads, block tile 128x128, thread tile 8x8, FFMA2
// ---------------------------------------------------------------
__global__ void __launch_bounds__(256, 2) sage_layer_kernel(
    const float* __restrict__ A,       // h_in  [NN, DD]
    const float* __restrict__ G,       // agg (pre-scaled) [NN, DD]
    const float* __restrict__ Wself,   // [DD, DD]
    const float* __restrict__ Wneigh,  // [DD, DD]
    const float* __restrict__ bias,    // [DD]
    float* __restrict__ out,           // [NN, DD]
    int do_relu)
{
    __shared__ float As[32][132];   // [k][row]
    __shared__ float Ws[32][132];   // [k][col]

    int tid = threadIdx.x;
    int tx = tid & 15;       // cols tx*8 .. +7
    int ty = tid >> 4;       // rows ty*8 .. +7
    int row0 = blockIdx.x * 128;

    unsigned long long acc2[4][8];   // [row-pair][col]
#pragma unroll
    for (int p = 0; p < 4; p++)
#pragma unroll
        for (int j = 0; j < 8; j++) acc2[p][j] = 0ull;

    for (int phase = 0; phase < 2; phase++) {
        const float* Ap = phase ? G : A;
        const float* Wp = phase ? Wneigh : Wself;
        for (int k0 = 0; k0 < DD; k0 += 32) {
            // A tile: 128 rows x 32 k, transposed into As[k][row]
#pragma unroll
            for (int i = 0; i < 4; i++) {
                int f = tid + i * 256;       // 0..1023 float4 slots
                int r = f >> 3;              // 0..127
                int kq = f & 7;              // k = kq*4
                int row = row0 + r;
                int rc = row < NN ? row : NN - 1;
                float4 v = *(const float4*)(Ap + (size_t)rc * DD + k0 + kq * 4);
                As[kq * 4 + 0][r] = v.x;
                As[kq * 4 + 1][r] = v.y;
                As[kq * 4 + 2][r] = v.z;
                As[kq * 4 + 3][r] = v.w;
            }
            // W tile: 32 k x 128 cols
#pragma unroll
            for (int i = 0; i < 4; i++) {
                int f = tid + i * 256;
                int k = f >> 5;
                int c4 = f & 31;
                *(float4*)&Ws[k][c4 * 4] =
                    *(const float4*)(Wp + (size_t)(k0 + k) * DD + c4 * 4);
            }
            __syncthreads();
#pragma unroll 8
            for (int k = 0; k < 32; k++) {
                ulonglong2 a01 = *(const ulonglong2*)&As[k][ty * 8];
                ulonglong2 a23 = *(const ulonglong2*)&As[k][ty * 8 + 4];
                float4 w0 = *(const float4*)&Ws[k][tx * 8];
                float4 w1 = *(const float4*)&Ws[k][tx * 8 + 4];
                unsigned long long wd[8];
                DUP2(wd[0], w0.x); DUP2(wd[1], w0.y); DUP2(wd[2], w0.z); DUP2(wd[3], w0.w);
                DUP2(wd[4], w1.x); DUP2(wd[5], w1.y); DUP2(wd[6], w1.z); DUP2(wd[7], w1.w);
                unsigned long long ra[4] = {a01.x, a01.y, a23.x, a23.y};
#pragma unroll
                for (int p = 0; p < 4; p++)
#pragma unroll
                    for (int j = 0; j < 8; j++)
                        FMA2(acc2[p][j], ra[p], wd[j]);
            }
            __syncthreads();
        }
    }

    int c0 = tx * 8;
    float4 b0 = *(const float4*)(bias + c0);
    float4 b1 = *(const float4*)(bias + c0 + 4);
    float bb[8] = {b0.x, b0.y, b0.z, b0.w, b1.x, b1.y, b1.z, b1.w};
#pragma unroll
    for (int p = 0; p < 4; p++) {
        float lo[8], hi[8];
#pragma unroll
        for (int j = 0; j < 8; j++) {
            UNPK2(lo[j], hi[j], acc2[p][j]);
            lo[j] += bb[j]; hi[j] += bb[j];
            if (do_relu) { lo[j] = fmaxf(lo[j], 0.f); hi[j] = fmaxf(hi[j], 0.f); }
        }
        int r = row0 + ty * 8 + 2 * p;
        if (r < NN) {
            float4 v0 = {lo[0], lo[1], lo[2], lo[3]};
            float4 v1 = {lo[4], lo[5], lo[6], lo[7]};
            *(float4*)(out + (size_t)r * DD + c0) = v0;
            *(float4*)(out + (size_t)r * DD + c0 + 4) = v1;
        }
        if (r + 1 < NN) {
            float4 v0 = {hi[0], hi[1], hi[2], hi[3]};
            float4 v1 = {hi[4], hi[5], hi[6], hi[7]};
            *(float4*)(out + (size_t)(r + 1) * DD + c0) = v0;
            *(float4*)(out + (size_t)(r + 1) * DD + c0 + 4) = v1;
        }
    }
}

// ---------------------------------------------------------------
// predictor: e = h[s]*h[d]; t1 = relu(e@Wp1+bp1); t2 = relu(t1@Wp2+bp2);
// out = t2@Wp3 + bp3.  128 pairs/block, 256 threads, 8x8 thread tile.
// dynamic smem: Es[128][132] + Ws[32][132]
// ---------------------------------------------------------------
__global__ void __launch_bounds__(256, 2) predictor_kernel(
    const float* __restrict__ h,
    const int* __restrict__ pos_src, const int* __restrict__ pos_dst,
    const int* __restrict__ neg_src, const int* __restrict__ neg_dst,
    const float* __restrict__ Wp1, const float* __restrict__ bp1,
    const float* __restrict__ Wp2, const float* __restrict__ bp2,
    const float* __restrict__ Wp3, const float* __restrict__ bp3,
    float* __restrict__ out)
{
    extern __shared__ float psmem[];
    float (*Es)[132] = (float(*)[132])psmem;                   // [128][132]
    float (*Ws)[132] = (float(*)[132])(psmem + 128 * 132);     // [32][132]

    int tid = threadIdx.x;
    int tx = tid & 15;
    int ty = tid >> 4;
    int g0 = blockIdx.x * 128;

    // ---- stage 1: e = h[src]*h[dst], transposed Es[k][pair] ----
    {
        int p = tid >> 1;        // 0..127 local pair
        int half = tid & 1;      // k half: half*64 .. +63
        int g = g0 + p;
        int gm = g < 2 * PP ? g : 2 * PP - 1;
        int s, d;
        if (gm < PP) { s = pos_src[gm]; d = pos_dst[gm]; }
        else         { s = neg_src[gm - PP]; d = neg_dst[gm - PP]; }
        const float4* hs = (const float4*)(h + (size_t)s * DD + half * 64);
        const float4* hd = (const float4*)(h + (size_t)d * DD + half * 64);
#pragma unroll
        for (int i = 0; i < 16; i++) {
            float4 a = hs[i];
            float4 bv = hd[i];
            int k = half * 64 + i * 4;
            Es[k + 0][p] = a.x * bv.x;
            Es[k + 1][p] = a.y * bv.y;
            Es[k + 2][p] = a.z * bv.z;
            Es[k + 3][p] = a.w * bv.w;
        }
    }

    unsigned long long acc2[4][8];

    // ================= GEMM 1: t1 = e @ Wp1 =================
#pragma unroll
    for (int p = 0; p < 4; p++)
#pragma unroll
        for (int j = 0; j < 8; j++) acc2[p][j] = 0ull;

    for (int k0 = 0; k0 < DD; k0 += 32) {
#pragma unroll
        for (int i = 0; i < 4; i++) {
            int f = tid + i * 256;
            int k = f >> 5, c4 = f & 31;
            *(float4*)&Ws[k][c4 * 4] =
                *(const float4*)(Wp1 + (size_t)(k0 + k) * DD + c4 * 4);
        }
        __syncthreads();
#pragma unroll 8
        for (int k = 0; k < 32; k++) {
            ulonglong2 a01 = *(const ulonglong2*)&Es[k0 + k][ty * 8];
            ulonglong2 a23 = *(const ulonglong2*)&Es[k0 + k][ty * 8 + 4];
            float4 w0 = *(const float4*)&Ws[k][tx * 8];
            float4 w1 = *(const float4*)&Ws[k][tx * 8 + 4];
            unsigned long long wd[8];
            DUP2(wd[0], w0.x); DUP2(wd[1], w0.y); DUP2(wd[2], w0.z); DUP2(wd[3], w0.w);
            DUP2(wd[4], w1.x); DUP2(wd[5], w1.y); DUP2(wd[6], w1.z); DUP2(wd[7], w1.w);
            unsigned long long ra[4] = {a01.x, a01.y, a23.x, a23.y};
#pragma unroll
            for (int p = 0; p < 4; p++)
#pragma unroll
                for (int j = 0; j < 8; j++)
                    FMA2(acc2[p][j], ra[p], wd[j]);
        }
        __syncthreads();
    }

    // ---- t1 = relu(acc + bp1), write transposed back into Es ----
    {
        int c0 = tx * 8;
        float4 b0 = *(const float4*)(bp1 + c0);
        float4 b1 = *(const float4*)(bp1 + c0 + 4);
        float bb[8] = {b0.x, b0.y, b0.z, b0.w, b1.x, b1.y, b1.z, b1.w};
#pragma unroll
        for (int p = 0; p < 4; p++) {
            float lo[8], hi[8];
#pragma unroll
            for (int j = 0; j < 8; j++) {
                UNPK2(lo[j], hi[j], acc2[p][j]);
                Es[c0 + j][ty * 8 + 2 * p]     = fmaxf(lo[j] + bb[j], 0.f);
                Es[c0 + j][ty * 8 + 2 * p + 1] = fmaxf(hi[j] + bb[j], 0.f);
            }
        }
    }
    __syncthreads();

    // ================= GEMM 2: t2 = t1 @ Wp2 =================
#pragma unroll
    for (int p = 0; p < 4; p++)
#pragma unroll
        for (int j = 0; j < 8; j++) acc2[p][j] = 0ull;

    for (int k0 = 0; k0 < DD; k0 += 32) {
#pragma unroll
        for (int i = 0; i < 4; i++) {
            int f = tid + i * 256;
            int k = f >> 5, c4 = f & 31;
            *(float4*)&Ws[k][c4 * 4] =
                *(const float4*)(Wp2 + (size_t)(k0 + k) * DD + c4 * 4);
        }
        __syncthreads();
#pragma unroll 8
        for (int k = 0; k < 32; k++) {
            ulonglong2 a01 = *(const ulonglong2*)&Es[k0 + k][ty * 8];
            ulonglong2 a23 = *(const ulonglong2*)&Es[k0 + k][ty * 8 + 4];
            float4 w0 = *(const float4*)&Ws[k][tx * 8];
            float4 w1 = *(const float4*)&Ws[k][tx * 8 + 4];
            unsigned long long wd[8];
            DUP2(wd[0], w0.x); DUP2(wd[1], w0.y); DUP2(wd[2], w0.z); DUP2(wd[3], w0.w);
            DUP2(wd[4], w1.x); DUP2(wd[5], w1.y); DUP2(wd[6], w1.z); DUP2(wd[7], w1.w);
            unsigned long long ra[4] = {a01.x, a01.y, a23.x, a23.y};
#pragma unroll
            for (int p = 0; p < 4; p++)
#pragma unroll
                for (int j = 0; j < 8; j++)
                    FMA2(acc2[p][j], ra[p], wd[j]);
        }
        __syncthreads();
    }

    // ---- t2 = relu(acc + bp2); score = t2 . Wp3 + bp3 ----
    int c0 = tx * 8;
    float4 b0 = *(const float4*)(bp2 + c0);
    float4 b1 = *(const float4*)(bp2 + c0 + 4);
    float bb[8] = {b0.x, b0.y, b0.z, b0.w, b1.x, b1.y, b1.z, b1.w};
    float4 w30 = *(const float4*)(Wp3 + c0);
    float4 w31 = *(const float4*)(Wp3 + c0 + 4);
    float w3[8] = {w30.x, w30.y, w30.z, w30.w, w31.x, w31.y, w31.z, w31.w};
    float part[8];
#pragma unroll
    for (int p = 0; p < 4; p++) {
        float lo[8], hi[8];
        float slo = 0.f, shi = 0.f;
#pragma unroll
        for (int j = 0; j < 8; j++) {
            UNPK2(lo[j], hi[j], acc2[p][j]);
            slo += fmaxf(lo[j] + bb[j], 0.f) * w3[j];
            shi += fmaxf(hi[j] + bb[j], 0.f) * w3[j];
        }
        part[2 * p] = slo;
        part[2 * p + 1] = shi;
    }
    // reduce across the 16 tx threads (lane bits 0..3)
#pragma unroll
    for (int off = 8; off; off >>= 1)
#pragma unroll
        for (int i = 0; i < 8; i++)
            part[i] += __shfl_xor_sync(0xffffffffu, part[i], off);

    if (tx == 0) {
        float b3 = bp3[0];
#pragma unroll
        for (int i = 0; i < 8; i++) {
            int g = g0 + ty * 8 + i;
            if (g < 2 * PP) out[g] = part[i] + b3;
        }
    }
}

// ---------------------------------------------------------------
// launch
// ---------------------------------------------------------------
extern "C" void kernel_launch(void* const* d_in, const int* in_sizes, int n_in,
                              void* d_out, int out_size) {
    const float* x       = (const float*)d_in[0];
    const float* W_self  = (const float*)d_in[1];
    const float* W_neigh = (const float*)d_in[2];
    const float* b       = (const float*)d_in[3];
    const float* Wp1     = (const float*)d_in[4];
    const float* bp1     = (const float*)d_in[5];
    const float* Wp2     = (const float*)d_in[6];
    const float* bp2     = (const float*)d_in[7];
    const float* Wp3     = (const float*)d_in[8];
    const float* bp3     = (const float*)d_in[9];
    const int* edge_src  = (const int*)d_in[10];
    const int* edge_dst  = (const int*)d_in[11];
    const int* pos_src   = (const int*)d_in[12];
    const int* pos_dst   = (const int*)d_in[13];
    const int* neg_src   = (const int*)d_in[14];
    const int* neg_dst   = (const int*)d_in[15];
    float* out = (float*)d_out;

    float *hA, *hB, *agg;
    int *deg;
    cudaGetSymbolAddress((void**)&hA, g_hA);
    cudaGetSymbolAddress((void**)&hB, g_hB);
    cudaGetSymbolAddress((void**)&agg, g_agg);
    cudaGetSymbolAddress((void**)&deg, g_deg);

    static int attr_done = 0;
    const int PRED_SMEM = (128 * 132 + 32 * 132) * (int)sizeof(float);  // 84480
    if (!attr_done) {
        cudaFuncSetAttribute(predictor_kernel,
                             cudaFuncAttributeMaxDynamicSharedMemorySize, PRED_SMEM);
        attr_done = 1;
    }

    // ---- CSR build ----
    cudaMemsetAsync(deg, 0, NN * sizeof(int));
    deg_count_kernel<<<(EE + 255) / 256, 256>>>(edge_dst);
    const int NB = (NN + 1023) / 1024;   // 49
    scan1_kernel<<<NB, 1024>>>();
    scan2_kernel<<<1, 32>>>(NB);
    scan3_kernel<<<(NN + 255) / 256, 256>>>();
    fill_kernel<<<(EE + 255) / 256, 256>>>(edge_src, edge_dst);

    // ---- layers ----
    const float* hin = x;
    float* outs[3] = {hA, hB, hA};
    for (int l = 0; l < 3; l++) {
        aggregate_kernel<<<(NN * 32 + 255) / 256, 256>>>(hin, agg);
        sage_layer_kernel<<<(NN + 127) / 128, 256>>>(
            hin, agg,
            W_self + (size_t)l * DD * DD,
            W_neigh + (size_t)l * DD * DD,
            b + (size_t)l * DD,
            outs[l], (l < 2) ? 1 : 0);
        hin = outs[l];
    }

    // ---- predictor ----
    predictor_kernel<<<(2 * PP + 127) / 128, 256, PRED_SMEM>>>(
        hin, pos_src, pos_dst, neg_src, neg_dst,
        Wp1, bp1, Wp2, bp2, Wp3, bp3, out);
}

// round 5
// speedup vs baseline: 2.0118x; 1.1642x over previous
#include <cuda_runtime.h>
#include <cuda_bf16.h>
#include <cstdint>

#define NN 50000
#define DD 128
#define EE 600000
#define PP 100000

// ---------------- packed f32x2 helpers (FFMA2 path, sage kernel) -------------
#define FMA2(acc, a, b) \
    asm("fma.rn.f32x2 %0, %1, %2, %0;" : "+l"(acc) : "l"(a), "l"(b))
#define DUP2(d, s) \
    asm("mov.b64 %0, {%1, %1};" : "=l"(d) : "f"(s))
#define UNPK2(lo, hi, v) \
    asm("mov.b64 {%0, %1}, %2;" : "=f"(lo), "=f"(hi) : "l"(v))

// ---------------- mma.sync helpers (sm_80-base ISA) --------------------------
__device__ __forceinline__ uint32_t smem_to_u32(const void* p) {
    uint32_t a;
    asm("{ .reg .u64 t; cvta.to.shared.u64 t, %1; cvt.u32.u64 %0, t; }"
        : "=r"(a) : "l"(p));
    return a;
}

#define LDSM_X4(r0, r1, r2, r3, addr) \
    asm volatile("ldmatrix.sync.aligned.m8n8.x4.shared.b16 {%0,%1,%2,%3}, [%4];" \
        : "=r"(r0), "=r"(r1), "=r"(r2), "=r"(r3) : "r"(addr))

#define MMA_BF16(d, a, b) \
    asm volatile("mma.sync.aligned.m16n8k16.row.col.f32.bf16.bf16.f32 " \
        "{%0,%1,%2,%3}, {%4,%5,%6,%7}, {%8,%9}, {%0,%1,%2,%3};" \
        : "+f"((d)[0]), "+f"((d)[1]), "+f"((d)[2]), "+f"((d)[3]) \
        : "r"((a)[0]), "r"((a)[1]), "r"((a)[2]), "r"((a)[3]), \
          "r"((b)[0]), "r"((b)[1]))

__device__ __forceinline__ void split2(float a, float b, uint32_t& hi, uint32_t& lo) {
    __nv_bfloat16 ha = __float2bfloat16(a), hb = __float2bfloat16(b);
    float ra = a - __bfloat162float(ha), rb = b - __bfloat162float(hb);
    __nv_bfloat162 H(ha, hb);
    __nv_bfloat162 L(__float2bfloat16(ra), __float2bfloat16(rb));
    hi = *reinterpret_cast<uint32_t*>(&H);
    lo = *reinterpret_cast<uint32_t*>(&L);
}

// ---- scratch (static device allocations; no runtime alloc) ----
__device__ float g_hA[NN * DD];
__device__ float g_hB[NN * DD];
__device__ float g_agg[NN * DD];
__device__ float g_invdeg[NN];
__device__ int   g_deg[NN];          // static zero-init; scan3 re-zeros each call
__device__ int   g_incl[NN];
__device__ int   g_bsum[64];
__device__ int   g_rows[NN + 1];
__device__ int   g_cursor[NN];
__device__ int   g_csr[EE];
// pre-split, pre-transposed predictor weights: WT[n*128+k] = W[k*128+n]
__device__ __align__(16) __nv_bfloat16 g_w1hi[DD * DD];
__device__ __align__(16) __nv_bfloat16 g_w1lo[DD * DD];
__device__ __align__(16) __nv_bfloat16 g_w2hi[DD * DD];
__device__ __align__(16) __nv_bfloat16 g_w2lo[DD * DD];

// ---------------------------------------------------------------
// CSR build
// ---------------------------------------------------------------
__global__ void deg_count_kernel(const int* __restrict__ dst) {
    int i = blockIdx.x * blockDim.x + threadIdx.x;
    if (i < EE) atomicAdd(&g_deg[dst[i]], 1);
}

__global__ void scan1_kernel() {
    __shared__ int sh[1024];
    int b = blockIdx.x, t = threadIdx.x;
    int i = b * 1024 + t;
    int v = (i < NN) ? g_deg[i] : 0;
    sh[t] = v;
    __syncthreads();
#pragma unroll
    for (int off = 1; off < 1024; off <<= 1) {
        int x = (t >= off) ? sh[t - off] : 0;
        __syncthreads();
        sh[t] += x;
        __syncthreads();
    }
    if (i < NN) g_incl[i] = sh[t];
    if (t == 1023) g_bsum[b] = sh[1023];
}

__global__ void scan2_kernel(int nb) {
    if (threadIdx.x == 0) {
        int s = 0;
        for (int b = 0; b < nb; b++) { int v = g_bsum[b]; g_bsum[b] = s; s += v; }
    }
}

__global__ void scan3_kernel() {
    int i = blockIdx.x * blockDim.x + threadIdx.x;
    if (i < NN) {
        int dg = g_deg[i];
        int excl = g_incl[i] - dg + g_bsum[i >> 10];
        g_rows[i] = excl;
        g_cursor[i] = excl;
        g_invdeg[i] = 1.0f / (float)max(dg, 1);
        g_deg[i] = 0;   // reset for the next kernel_launch call (replaces memset)
    }
    if (i == 0) g_rows[NN] = EE;
}

__global__ void fill_kernel(const int* __restrict__ src, const int* __restrict__ dst) {
    int e = blockIdx.x * blockDim.x + threadIdx.x;
    if (e < EE) {
        int p = atomicAdd(&g_cursor[dst[e]], 1);
        g_csr[p] = src[e];
    }
}

// ---------------------------------------------------------------
// weight prep: split+transpose Wp1/Wp2 into bf16 hi/lo [N,K] row-major
// ---------------------------------------------------------------
__global__ void prep_w_kernel(const float* __restrict__ Wp1,
                              const float* __restrict__ Wp2) {
    int idx = blockIdx.x * blockDim.x + threadIdx.x;
    if (idx >= DD * DD) return;
    int n = idx >> 7, k = idx & 127;
    {
        float v = Wp1[k * DD + n];
        __nv_bfloat16 hi = __float2bfloat16(v);
        g_w1hi[n * DD + k] = hi;
        g_w1lo[n * DD + k] = __float2bfloat16(v - __bfloat162float(hi));
    }
    {
        float v = Wp2[k * DD + n];
        __nv_bfloat16 hi = __float2bfloat16(v);
        g_w2hi[n * DD + k] = hi;
        g_w2lo[n * DD + k] = __float2bfloat16(v - __bfloat162float(hi));
    }
}

// ---------------------------------------------------------------
// aggregate: agg[n] = invdeg[n] * sum_{e in CSR(n)} h[src_e]
// ---------------------------------------------------------------
__global__ void aggregate_kernel(const float* __restrict__ h, float* __restrict__ agg) {
    int w = (blockIdx.x * blockDim.x + threadIdx.x) >> 5;
    int lane = threadIdx.x & 31;
    if (w >= NN) return;
    int rs = g_rows[w], re = g_rows[w + 1];
    float4 acc = {0.f, 0.f, 0.f, 0.f};
    int i = rs;
    for (; i + 3 < re; i += 4) {
        int s0 = __ldg(&g_csr[i]);
        int s1 = __ldg(&g_csr[i + 1]);
        int s2 = __ldg(&g_csr[i + 2]);
        int s3 = __ldg(&g_csr[i + 3]);
        float4 a = __ldg((const float4*)(h + (size_t)s0 * DD) + lane);
        float4 b = __ldg((const float4*)(h + (size_t)s1 * DD) + lane);
        float4 c = __ldg((const float4*)(h + (size_t)s2 * DD) + lane);
        float4 d = __ldg((const float4*)(h + (size_t)s3 * DD) + lane);
        acc.x += a.x + b.x + c.x + d.x;
        acc.y += a.y + b.y + c.y + d.y;
        acc.z += a.z + b.z + c.z + d.z;
        acc.w += a.w + b.w + c.w + d.w;
    }
    for (; i < re; i++) {
        int s0 = __ldg(&g_csr[i]);
        float4 a = __ldg((const float4*)(h + (size_t)s0 * DD) + lane);
        acc.x += a.x; acc.y += a.y; acc.z += a.z; acc.w += a.w;
    }
    float sc = g_invdeg[w];
    acc.x *= sc; acc.y *= sc; acc.z *= sc; acc.w *= sc;
    ((float4*)(agg + (size_t)w * DD))[lane] = acc;
}

// ---------------------------------------------------------------
// fused SAGE layer (FFMA2, unchanged — known good)
// ---------------------------------------------------------------
__global__ void __launch_bounds__(256, 2) sage_layer_kernel(
    const float* __restrict__ A,
    const float* __restrict__ G,
    const float* __restrict__ Wself,
    const float* __restrict__ Wneigh,
    const float* __restrict__ bias,
    float* __restrict__ out,
    int do_relu)
{
    __shared__ float As[32][132];
    __shared__ float Ws[32][132];

    int tid = threadIdx.x;
    int tx = tid & 15;
    int ty = tid >> 4;
    int row0 = blockIdx.x * 128;

    unsigned long long acc2[4][8];
#pragma unroll
    for (int p = 0; p < 4; p++)
#pragma unroll
        for (int j = 0; j < 8; j++) acc2[p][j] = 0ull;

    for (int phase = 0; phase < 2; phase++) {
        const float* Ap = phase ? G : A;
        const float* Wp = phase ? Wneigh : Wself;
        for (int k0 = 0; k0 < DD; k0 += 32) {
#pragma unroll
            for (int i = 0; i < 4; i++) {
                int f = tid + i * 256;
                int r = f >> 3;
                int kq = f & 7;
                int row = row0 + r;
                int rc = row < NN ? row : NN - 1;
                float4 v = *(const float4*)(Ap + (size_t)rc * DD + k0 + kq * 4);
                As[kq * 4 + 0][r] = v.x;
                As[kq * 4 + 1][r] = v.y;
                As[kq * 4 + 2][r] = v.z;
                As[kq * 4 + 3][r] = v.w;
            }
#pragma unroll
            for (int i = 0; i < 4; i++) {
                int f = tid + i * 256;
                int k = f >> 5;
                int c4 = f & 31;
                *(float4*)&Ws[k][c4 * 4] =
                    *(const float4*)(Wp + (size_t)(k0 + k) * DD + c4 * 4);
            }
            __syncthreads();
#pragma unroll 8
            for (int k = 0; k < 32; k++) {
                ulonglong2 a01 = *(const ulonglong2*)&As[k][ty * 8];
                ulonglong2 a23 = *(const ulonglong2*)&As[k][ty * 8 + 4];
                float4 w0 = *(const float4*)&Ws[k][tx * 8];
                float4 w1 = *(const float4*)&Ws[k][tx * 8 + 4];
                unsigned long long wd[8];
                DUP2(wd[0], w0.x); DUP2(wd[1], w0.y); DUP2(wd[2], w0.z); DUP2(wd[3], w0.w);
                DUP2(wd[4], w1.x); DUP2(wd[5], w1.y); DUP2(wd[6], w1.z); DUP2(wd[7], w1.w);
                unsigned long long ra[4] = {a01.x, a01.y, a23.x, a23.y};
#pragma unroll
                for (int p = 0; p < 4; p++)
#pragma unroll
                    for (int j = 0; j < 8; j++)
                        FMA2(acc2[p][j], ra[p], wd[j]);
            }
            __syncthreads();
        }
    }

    int c0 = tx * 8;
    float4 b0 = *(const float4*)(bias + c0);
    float4 b1 = *(const float4*)(bias + c0 + 4);
    float bb[8] = {b0.x, b0.y, b0.z, b0.w, b1.x, b1.y, b1.z, b1.w};
#pragma unroll
    for (int p = 0; p < 4; p++) {
        float lo[8], hi[8];
#pragma unroll
        for (int j = 0; j < 8; j++) {
            UNPK2(lo[j], hi[j], acc2[p][j]);
            lo[j] += bb[j]; hi[j] += bb[j];
            if (do_relu) { lo[j] = fmaxf(lo[j], 0.f); hi[j] = fmaxf(hi[j], 0.f); }
        }
        int r = row0 + ty * 8 + 2 * p;
        if (r < NN) {
            float4 v0 = {lo[0], lo[1], lo[2], lo[3]};
            float4 v1 = {lo[4], lo[5], lo[6], lo[7]};
            *(float4*)(out + (size_t)r * DD + c0) = v0;
            *(float4*)(out + (size_t)r * DD + c0 + 4) = v1;
        }
        if (r + 1 < NN) {
            float4 v0 = {hi[0], hi[1], hi[2], hi[3]};
            float4 v1 = {hi[4], hi[5], hi[6], hi[7]};
            *(float4*)(out + (size_t)(r + 1) * DD + c0) = v0;
            *(float4*)(out + (size_t)(r + 1) * DD + c0 + 4) = v1;
        }
    }
}

// ---------------------------------------------------------------
// predictor via mma.sync (split-bf16, 3-term): 128 pairs/block,
// 8 warps, warp tile 32(M) x 64(N), K=128.
// smem: Ahi/Alo/Bhi/Blo each [128][136] bf16 = 4 x 34816 B = 139264 B
// ---------------------------------------------------------------
#define STR 136

__global__ void __launch_bounds__(256) predictor_mma_kernel(
    const float* __restrict__ h,
    const int* __restrict__ pos_src, const int* __restrict__ pos_dst,
    const int* __restrict__ neg_src, const int* __restrict__ neg_dst,
    const float* __restrict__ bp1, const float* __restrict__ bp2,
    const float* __restrict__ Wp3, const float* __restrict__ bp3,
    float* __restrict__ out)
{
    extern __shared__ __nv_bfloat16 bsm[];
    __nv_bfloat16* Ahi = bsm;
    __nv_bfloat16* Alo = bsm + 128 * STR;
    __nv_bfloat16* Bhi = bsm + 2 * 128 * STR;
    __nv_bfloat16* Blo = bsm + 3 * 128 * STR;
    __shared__ float s_b1[DD], s_b2[DD], s_w3[DD];
    __shared__ float s_part[DD][2];

    int tid = threadIdx.x;
    int lane = tid & 31;
    int wid = tid >> 5;
    int wm = wid >> 1, wn = wid & 1;
    int m0 = wm * 32, n0 = wn * 64;
    int g0 = blockIdx.x * 128;

    if (tid < DD) {
        s_b1[tid] = bp1[tid];
        s_b2[tid] = bp2[tid];
        s_w3[tid] = Wp3[tid];
    }

    // ---- stage 1: A = split(h[s]*h[d]), B = split(W1^T) ----
    {
        int p = tid >> 1;
        int half = tid & 1;
        int g = g0 + p;
        int gm = g < 2 * PP ? g : 2 * PP - 1;
        int s, d;
        if (gm < PP) { s = pos_src[gm]; d = pos_dst[gm]; }
        else         { s = neg_src[gm - PP]; d = neg_dst[gm - PP]; }
        const float4* hs = (const float4*)(h + (size_t)s * DD + half * 64);
        const float4* hd = (const float4*)(h + (size_t)d * DD + half * 64);
#pragma unroll
        for (int i = 0; i < 16; i++) {
            float4 a = hs[i];
            float4 bv = hd[i];
            float e0 = a.x * bv.x, e1 = a.y * bv.y, e2 = a.z * bv.z, e3 = a.w * bv.w;
            uint32_t h01, l01, h23, l23;
            split2(e0, e1, h01, l01);
            split2(e2, e3, h23, l23);
            int k = half * 64 + i * 4;
            uint2 vh = {h01, h23};
            uint2 vl = {l01, l23};
            *(uint2*)&Ahi[p * STR + k] = vh;
            *(uint2*)&Alo[p * STR + k] = vl;
        }
        // W1 tiles (row n = output col, k contiguous)
        int n = tid >> 1;
        const uint2* w1h = (const uint2*)g_w1hi + n * 32 + half * 16;
        const uint2* w1l = (const uint2*)g_w1lo + n * 32 + half * 16;
#pragma unroll
        for (int i = 0; i < 16; i++) {
            int k = half * 64 + i * 4;
            *(uint2*)&Bhi[n * STR + k] = w1h[i];
            *(uint2*)&Blo[n * STR + k] = w1l[i];
        }
    }
    __syncthreads();

    uint32_t sAhi = smem_to_u32(Ahi), sAlo = smem_to_u32(Alo);
    uint32_t sBhi = smem_to_u32(Bhi), sBlo = smem_to_u32(Blo);
    int rA = m0 + (lane & 15);
    int rB = n0 + (lane & 15);
    int cOff = (lane >> 4) * 8;
    int gq = lane >> 2, tq = lane & 3;

    float acc[2][8][4];

    // ================= GEMM 1 =================
#pragma unroll
    for (int mf = 0; mf < 2; mf++)
#pragma unroll
        for (int nf = 0; nf < 8; nf++)
#pragma unroll
            for (int j = 0; j < 4; j++) acc[mf][nf][j] = 0.f;

#pragma unroll
    for (int ks = 0; ks < 8; ks++) {
        int k0 = ks * 16;
        uint32_t ah[2][4], al[2][4], bh[8][2], bl[8][2];
#pragma unroll
        for (int mf = 0; mf < 2; mf++) {
            uint32_t ad = sAhi + ((rA + mf * 16) * STR + k0 + cOff) * 2;
            LDSM_X4(ah[mf][0], ah[mf][1], ah[mf][2], ah[mf][3], ad);
            uint32_t ad2 = sAlo + ((rA + mf * 16) * STR + k0 + cOff) * 2;
            LDSM_X4(al[mf][0], al[mf][1], al[mf][2], al[mf][3], ad2);
        }
#pragma unroll
        for (int q = 0; q < 4; q++) {
            uint32_t bd = sBhi + ((rB + q * 16) * STR + k0 + cOff) * 2;
            uint32_t t0, t1, t2, t3;
            LDSM_X4(t0, t1, t2, t3, bd);
            bh[2 * q][0] = t0; bh[2 * q + 1][0] = t1;
            bh[2 * q][1] = t2; bh[2 * q + 1][1] = t3;
            uint32_t bd2 = sBlo + ((rB + q * 16) * STR + k0 + cOff) * 2;
            LDSM_X4(t0, t1, t2, t3, bd2);
            bl[2 * q][0] = t0; bl[2 * q + 1][0] = t1;
            bl[2 * q][1] = t2; bl[2 * q + 1][1] = t3;
        }
#pragma unroll
        for (int mf = 0; mf < 2; mf++)
#pragma unroll
            for (int nf = 0; nf < 8; nf++) {
                MMA_BF16(acc[mf][nf], ah[mf], bh[nf]);
                MMA_BF16(acc[mf][nf], ah[mf], bl[nf]);
                MMA_BF16(acc[mf][nf], al[mf], bh[nf]);
            }
    }
    __syncthreads();   // all GEMM1 smem reads complete

    // ---- epilogue1: t1 = relu(D + bp1) split back into A tiles; load W2 ----
#pragma unroll
    for (int mf = 0; mf < 2; mf++) {
        int r1 = m0 + mf * 16 + gq;
        int r2 = r1 + 8;
#pragma unroll
        for (int nf = 0; nf < 8; nf++) {
            int c = n0 + nf * 8 + 2 * tq;
            float v0 = fmaxf(acc[mf][nf][0] + s_b1[c], 0.f);
            float v1 = fmaxf(acc[mf][nf][1] + s_b1[c + 1], 0.f);
            float v2 = fmaxf(acc[mf][nf][2] + s_b1[c], 0.f);
            float v3 = fmaxf(acc[mf][nf][3] + s_b1[c + 1], 0.f);
            uint32_t hh, ll;
            split2(v0, v1, hh, ll);
            *(uint32_t*)&Ahi[r1 * STR + c] = hh;
            *(uint32_t*)&Alo[r1 * STR + c] = ll;
            split2(v2, v3, hh, ll);
            *(uint32_t*)&Ahi[r2 * STR + c] = hh;
            *(uint32_t*)&Alo[r2 * STR + c] = ll;
        }
    }
    {
        int n = tid >> 1;
        int half = tid & 1;
        const uint2* w2h = (const uint2*)g_w2hi + n * 32 + half * 16;
        const uint2* w2l = (const uint2*)g_w2lo + n * 32 + half * 16;
#pragma unroll
        for (int i = 0; i < 16; i++) {
            int k = half * 64 + i * 4;
            *(uint2*)&Bhi[n * STR + k] = w2h[i];
            *(uint2*)&Blo[n * STR + k] = w2l[i];
        }
    }
    __syncthreads();

    // ================= GEMM 2 =================
#pragma unroll
    for (int mf = 0; mf < 2; mf++)
#pragma unroll
        for (int nf = 0; nf < 8; nf++)
#pragma unroll
            for (int j = 0; j < 4; j++) acc[mf][nf][j] = 0.f;

#pragma unroll
    for (int ks = 0; ks < 8; ks++) {
        int k0 = ks * 16;
        uint32_t ah[2][4], al[2][4], bh[8][2], bl[8][2];
#pragma unroll
        for (int mf = 0; mf < 2; mf++) {
            uint32_t ad = sAhi + ((rA + mf * 16) * STR + k0 + cOff) * 2;
            LDSM_X4(ah[mf][0], ah[mf][1], ah[mf][2], ah[mf][3], ad);
            uint32_t ad2 = sAlo + ((rA + mf * 16) * STR + k0 + cOff) * 2;
            LDSM_X4(al[mf][0], al[mf][1], al[mf][2], al[mf][3], ad2);
        }
#pragma unroll
        for (int q = 0; q < 4; q++) {
            uint32_t bd = sBhi + ((rB + q * 16) * STR + k0 + cOff) * 2;
            uint32_t t0, t1, t2, t3;
            LDSM_X4(t0, t1, t2, t3, bd);
            bh[2 * q][0] = t0; bh[2 * q + 1][0] = t1;
            bh[2 * q][1] = t2; bh[2 * q + 1][1] = t3;
            uint32_t bd2 = sBlo + ((rB + q * 16) * STR + k0 + cOff) * 2;
            LDSM_X4(t0, t1, t2, t3, bd2);
            bl[2 * q][0] = t0; bl[2 * q + 1][0] = t1;
            bl[2 * q][1] = t2; bl[2 * q + 1][1] = t3;
        }
#pragma unroll
        for (int mf = 0; mf < 2; mf++)
#pragma unroll
            for (int nf = 0; nf < 8; nf++) {
                MMA_BF16(acc[mf][nf], ah[mf], bh[nf]);
                MMA_BF16(acc[mf][nf], ah[mf], bl[nf]);
                MMA_BF16(acc[mf][nf], al[mf], bh[nf]);
            }
    }

    // ---- epilogue2: score = relu(D + bp2) . w3 (+bp3) ----
#pragma unroll
    for (int mf = 0; mf < 2; mf++) {
        float p0 = 0.f, p1 = 0.f;
#pragma unroll
        for (int nf = 0; nf < 8; nf++) {
            int c = n0 + nf * 8 + 2 * tq;
            p0 += fmaxf(acc[mf][nf][0] + s_b2[c], 0.f) * s_w3[c]
                + fmaxf(acc[mf][nf][1] + s_b2[c + 1], 0.f) * s_w3[c + 1];
            p1 += fmaxf(acc[mf][nf][2] + s_b2[c], 0.f) * s_w3[c]
                + fmaxf(acc[mf][nf][3] + s_b2[c + 1], 0.f) * s_w3[c + 1];
        }
        p0 += __shfl_xor_sync(0xffffffffu, p0, 1);
        p0 += __shfl_xor_sync(0xffffffffu, p0, 2);
        p1 += __shfl_xor_sync(0xffffffffu, p1, 1);
        p1 += __shfl_xor_sync(0xffffffffu, p1, 2);
        if (tq == 0) {
            s_part[m0 + mf * 16 + gq][wn] = p0;
            s_part[m0 + mf * 16 + gq + 8][wn] = p1;
        }
    }
    __syncthreads();
    if (tid < 128) {
        int g = g0 + tid;
        if (g < 2 * PP) out[g] = s_part[tid][0] + s_part[tid][1] + bp3[0];
    }
}

// ---------------------------------------------------------------
// launch
// ---------------------------------------------------------------
extern "C" void kernel_launch(void* const* d_in, const int* in_sizes, int n_in,
                              void* d_out, int out_size) {
    const float* x       = (const float*)d_in[0];
    const float* W_self  = (const float*)d_in[1];
    const float* W_neigh = (const float*)d_in[2];
    const float* b       = (const float*)d_in[3];
    const float* Wp1     = (const float*)d_in[4];
    const float* bp1     = (const float*)d_in[5];
    const float* Wp2     = (const float*)d_in[6];
    const float* bp2     = (const float*)d_in[7];
    const float* Wp3     = (const float*)d_in[8];
    const float* bp3     = (const float*)d_in[9];
    const int* edge_src  = (const int*)d_in[10];
    const int* edge_dst  = (const int*)d_in[11];
    const int* pos_src   = (const int*)d_in[12];
    const int* pos_dst   = (const int*)d_in[13];
    const int* neg_src   = (const int*)d_in[14];
    const int* neg_dst   = (const int*)d_in[15];
    float* out = (float*)d_out;

    float *hA, *hB, *agg;
    cudaGetSymbolAddress((void**)&hA, g_hA);
    cudaGetSymbolAddress((void**)&hB, g_hB);
    cudaGetSymbolAddress((void**)&agg, g_agg);

    static int attr_done = 0;
    const int PRED_SMEM = 4 * 128 * STR * 2;   // 139264
    if (!attr_done) {
        cudaFuncSetAttribute(predictor_mma_kernel,
                             cudaFuncAttributeMaxDynamicSharedMemorySize, PRED_SMEM);
        attr_done = 1;
    }

    // ---- CSR build (g_deg is zeroed by previous call's scan3 / static init) ----
    deg_count_kernel<<<(EE + 255) / 256, 256>>>(edge_dst);              // 0
    const int NB = (NN + 1023) / 1024;
    scan1_kernel<<<NB, 1024>>>();                                       // 1
    scan2_kernel<<<1, 32>>>(NB);                                        // 2
    scan3_kernel<<<(NN + 255) / 256, 256>>>();                          // 3
    fill_kernel<<<(EE + 255) / 256, 256>>>(edge_src, edge_dst);         // 4

    // ---- layers ----
    const float* hin = x;
    float* outs[3] = {hA, hB, hA};
    for (int l = 0; l < 3; l++) {
        aggregate_kernel<<<(NN * 32 + 255) / 256, 256>>>(hin, agg);     // 5 = agg0 (ncu target)
        sage_layer_kernel<<<(NN + 127) / 128, 256>>>(
            hin, agg,
            W_self + (size_t)l * DD * DD,
            W_neigh + (size_t)l * DD * DD,
            b + (size_t)l * DD,
            outs[l], (l < 2) ? 1 : 0);
        hin = outs[l];
    }

    // ---- predictor weight prep + predictor ----
    prep_w_kernel<<<(DD * DD + 255) / 256, 256>>>(Wp1, Wp2);
    predictor_mma_kernel<<<(2 * PP + 127) / 128, 256, PRED_SMEM>>>(
        hin, pos_src, pos_dst, neg_src, neg_dst,
        bp1, bp2, Wp3, bp3, out);
}

// round 6
// speedup vs baseline: 2.2448x; 1.1158x over previous
#include <cuda_runtime.h>
#include <cuda_bf16.h>
#include <cstdint>

#define NN 50000
#define DD 128
#define EE 600000
#define PP 100000
#define STR 136

// ---------------- mma.sync helpers (sm_80-base ISA) --------------------------
__device__ __forceinline__ uint32_t smem_to_u32(const void* p) {
    uint32_t a;
    asm("{ .reg .u64 t; cvta.to.shared.u64 t, %1; cvt.u32.u64 %0, t; }"
        : "=r"(a) : "l"(p));
    return a;
}

#define LDSM_X4(r0, r1, r2, r3, addr) \
    asm volatile("ldmatrix.sync.aligned.m8n8.x4.shared.b16 {%0,%1,%2,%3}, [%4];" \
        : "=r"(r0), "=r"(r1), "=r"(r2), "=r"(r3) : "r"(addr))

#define MMA_BF16(d, a, b) \
    asm volatile("mma.sync.aligned.m16n8k16.row.col.f32.bf16.bf16.f32 " \
        "{%0,%1,%2,%3}, {%4,%5,%6,%7}, {%8,%9}, {%0,%1,%2,%3};" \
        : "+f"((d)[0]), "+f"((d)[1]), "+f"((d)[2]), "+f"((d)[3]) \
        : "r"((a)[0]), "r"((a)[1]), "r"((a)[2]), "r"((a)[3]), \
          "r"((b)[0]), "r"((b)[1]))

__device__ __forceinline__ void split2(float a, float b, uint32_t& hi, uint32_t& lo) {
    __nv_bfloat16 ha = __float2bfloat16(a), hb = __float2bfloat16(b);
    float ra = a - __bfloat162float(ha), rb = b - __bfloat162float(hb);
    __nv_bfloat162 H(ha, hb);
    __nv_bfloat162 L(__float2bfloat16(ra), __float2bfloat16(rb));
    hi = *reinterpret_cast<uint32_t*>(&H);
    lo = *reinterpret_cast<uint32_t*>(&L);
}

// ---- scratch (static device allocations; no runtime alloc) ----
__device__ float g_hA[NN * DD];
__device__ float g_hB[NN * DD];
__device__ float g_agg[NN * DD];
__device__ float g_invdeg[NN];
__device__ int   g_deg[NN];          // zero at start of each launch via scan3 reset
__device__ int   g_incl[NN];
__device__ int   g_bsum[64];
__device__ int   g_rows[NN + 1];
__device__ int   g_cursor[NN];
__device__ int   g_csr[EE];
// pre-split, pre-transposed weights: WT[n*128+k] = W[k*128+n]
__device__ __align__(16) __nv_bfloat16 g_w1hi[DD * DD];
__device__ __align__(16) __nv_bfloat16 g_w1lo[DD * DD];
__device__ __align__(16) __nv_bfloat16 g_w2hi[DD * DD];
__device__ __align__(16) __nv_bfloat16 g_w2lo[DD * DD];
// sage weights: index (l*2 + phase)*DD*DD, phase0=self, phase1=neigh
__device__ __align__(16) __nv_bfloat16 g_swhi[6 * DD * DD];
__device__ __align__(16) __nv_bfloat16 g_swlo[6 * DD * DD];

// ---------------------------------------------------------------
// CSR build
// ---------------------------------------------------------------
__global__ void deg_count_kernel(const int* __restrict__ dst) {
    int i = blockIdx.x * blockDim.x + threadIdx.x;
    if (i < EE) atomicAdd(&g_deg[dst[i]], 1);
}

__global__ void scan1_kernel() {
    __shared__ int sh[1024];
    int b = blockIdx.x, t = threadIdx.x;
    int i = b * 1024 + t;
    int v = (i < NN) ? g_deg[i] : 0;
    sh[t] = v;
    __syncthreads();
#pragma unroll
    for (int off = 1; off < 1024; off <<= 1) {
        int x = (t >= off) ? sh[t - off] : 0;
        __syncthreads();
        sh[t] += x;
        __syncthreads();
    }
    if (i < NN) g_incl[i] = sh[t];
    if (t == 1023) g_bsum[b] = sh[1023];
}

__global__ void scan2_kernel(int nb) {
    if (threadIdx.x == 0) {
        int s = 0;
        for (int b = 0; b < nb; b++) { int v = g_bsum[b]; g_bsum[b] = s; s += v; }
    }
}

__global__ void scan3_kernel() {
    int i = blockIdx.x * blockDim.x + threadIdx.x;
    if (i < NN) {
        int dg = g_deg[i];
        int excl = g_incl[i] - dg + g_bsum[i >> 10];
        g_rows[i] = excl;
        g_cursor[i] = excl;
        g_invdeg[i] = 1.0f / (float)max(dg, 1);
        g_deg[i] = 0;   // reset for next launch
    }
    if (i == 0) g_rows[NN] = EE;
}

__global__ void fill_kernel(const int* __restrict__ src, const int* __restrict__ dst) {
    int e = blockIdx.x * blockDim.x + threadIdx.x;
    if (e < EE) {
        int p = atomicAdd(&g_cursor[dst[e]], 1);
        g_csr[p] = src[e];
    }
}

// ---------------------------------------------------------------
// weight prep: split + transpose all GEMM weights into bf16 hi/lo [N,K]
// ---------------------------------------------------------------
__global__ void prep_w_kernel(const float* __restrict__ W_self,
                              const float* __restrict__ W_neigh,
                              const float* __restrict__ Wp1,
                              const float* __restrict__ Wp2) {
    int idx = blockIdx.x * blockDim.x + threadIdx.x;
    if (idx >= 3 * DD * DD) return;
    int l = idx >> 14;
    int r = idx & (DD * DD - 1);
    int n = r >> 7, k = r & 127;
    {
        float v = W_self[l * DD * DD + k * DD + n];
        __nv_bfloat16 hi = __float2bfloat16(v);
        g_swhi[(l * 2 + 0) * DD * DD + n * DD + k] = hi;
        g_swlo[(l * 2 + 0) * DD * DD + n * DD + k] =
            __float2bfloat16(v - __bfloat162float(hi));
    }
    {
        float v = W_neigh[l * DD * DD + k * DD + n];
        __nv_bfloat16 hi = __float2bfloat16(v);
        g_swhi[(l * 2 + 1) * DD * DD + n * DD + k] = hi;
        g_swlo[(l * 2 + 1) * DD * DD + n * DD + k] =
            __float2bfloat16(v - __bfloat162float(hi));
    }
    if (l == 0) {
        float v = Wp1[k * DD + n];
        __nv_bfloat16 hi = __float2bfloat16(v);
        g_w1hi[n * DD + k] = hi;
        g_w1lo[n * DD + k] = __float2bfloat16(v - __bfloat162float(hi));
        v = Wp2[k * DD + n];
        hi = __float2bfloat16(v);
        g_w2hi[n * DD + k] = hi;
        g_w2lo[n * DD + k] = __float2bfloat16(v - __bfloat162float(hi));
    }
}

// ---------------------------------------------------------------
// aggregate: agg[n] = invdeg[n] * sum_{e in CSR(n)} h[src_e]
// ---------------------------------------------------------------
__global__ void aggregate_kernel(const float* __restrict__ h, float* __restrict__ agg) {
    int w = (blockIdx.x * blockDim.x + threadIdx.x) >> 5;
    int lane = threadIdx.x & 31;
    if (w >= NN) return;
    int rs = g_rows[w], re = g_rows[w + 1];
    float4 acc = {0.f, 0.f, 0.f, 0.f};
    int i = rs;
    for (; i + 3 < re; i += 4) {
        int s0 = __ldg(&g_csr[i]);
        int s1 = __ldg(&g_csr[i + 1]);
        int s2 = __ldg(&g_csr[i + 2]);
        int s3 = __ldg(&g_csr[i + 3]);
        float4 a = __ldg((const float4*)(h + (size_t)s0 * DD) + lane);
        float4 b = __ldg((const float4*)(h + (size_t)s1 * DD) + lane);
        float4 c = __ldg((const float4*)(h + (size_t)s2 * DD) + lane);
        float4 d = __ldg((const float4*)(h + (size_t)s3 * DD) + lane);
        acc.x += a.x + b.x + c.x + d.x;
        acc.y += a.y + b.y + c.y + d.y;
        acc.z += a.z + b.z + c.z + d.z;
        acc.w += a.w + b.w + c.w + d.w;
    }
    for (; i < re; i++) {
        int s0 = __ldg(&g_csr[i]);
        float4 a = __ldg((const float4*)(h + (size_t)s0 * DD) + lane);
        acc.x += a.x; acc.y += a.y; acc.z += a.z; acc.w += a.w;
    }
    float sc = g_invdeg[w];
    acc.x *= sc; acc.y *= sc; acc.z *= sc; acc.w *= sc;
    ((float4*)(agg + (size_t)w * DD))[lane] = acc;
}

// ---------------------------------------------------------------
// sage layer via mma.sync (split-bf16 3-term):
// out = act( h @ Wself + agg @ Wneigh + b )
// 128 rows/block, 8 warps, warp tile 32x64, two K=128 phases into same acc.
// ---------------------------------------------------------------
__global__ void __launch_bounds__(256) sage_mma_kernel(
    const float* __restrict__ A,       // h_in
    const float* __restrict__ G,       // agg (pre-scaled)
    const float* __restrict__ bias,
    float* __restrict__ out,
    int do_relu, int layer)
{
    extern __shared__ __nv_bfloat16 bsm[];
    __nv_bfloat16* Ahi = bsm;
    __nv_bfloat16* Alo = bsm + 128 * STR;
    __nv_bfloat16* Bhi = bsm + 2 * 128 * STR;
    __nv_bfloat16* Blo = bsm + 3 * 128 * STR;
    __shared__ float s_bias[DD];

    int tid = threadIdx.x;
    int lane = tid & 31;
    int wid = tid >> 5;
    int wm = wid >> 1, wn = wid & 1;
    int m0 = wm * 32, n0 = wn * 64;
    int row0 = blockIdx.x * 128;

    if (tid < DD) s_bias[tid] = bias[tid];

    uint32_t sAhi = smem_to_u32(Ahi), sAlo = smem_to_u32(Alo);
    uint32_t sBhi = smem_to_u32(Bhi), sBlo = smem_to_u32(Blo);
    int rA = m0 + (lane & 15);
    int rB = n0 + (lane & 15);
    int cOff = (lane >> 4) * 8;
    int gq = lane >> 2, tq = lane & 3;

    float acc[2][8][4];
#pragma unroll
    for (int mf = 0; mf < 2; mf++)
#pragma unroll
        for (int nf = 0; nf < 8; nf++)
#pragma unroll
            for (int j = 0; j < 4; j++) acc[mf][nf][j] = 0.f;

    int p = tid >> 1;
    int half = tid & 1;
    int rc = min(row0 + p, NN - 1);

    for (int phase = 0; phase < 2; phase++) {
        const float* Ap = phase ? G : A;
        const __nv_bfloat16* Whi = g_swhi + (size_t)(layer * 2 + phase) * DD * DD;
        const __nv_bfloat16* Wlo = g_swlo + (size_t)(layer * 2 + phase) * DD * DD;

        // ---- stage: A tile split ----
        const float4* hs = (const float4*)(Ap + (size_t)rc * DD + half * 64);
#pragma unroll
        for (int i = 0; i < 16; i++) {
            float4 v = hs[i];
            uint32_t h01, l01, h23, l23;
            split2(v.x, v.y, h01, l01);
            split2(v.z, v.w, h23, l23);
            int k = half * 64 + i * 4;
            uint2 vh = {h01, h23};
            uint2 vl = {l01, l23};
            *(uint2*)&Ahi[p * STR + k] = vh;
            *(uint2*)&Alo[p * STR + k] = vl;
        }
        // ---- stage: B tile (pre-split weights) ----
        {
            const uint2* wh = (const uint2*)Whi + p * 32 + half * 16;
            const uint2* wl = (const uint2*)Wlo + p * 32 + half * 16;
#pragma unroll
            for (int i = 0; i < 16; i++) {
                int k = half * 64 + i * 4;
                *(uint2*)&Bhi[p * STR + k] = wh[i];
                *(uint2*)&Blo[p * STR + k] = wl[i];
            }
        }
        __syncthreads();

        // ---- GEMM accumulate ----
#pragma unroll
        for (int ks = 0; ks < 8; ks++) {
            int k0 = ks * 16;
            uint32_t ah[2][4], al[2][4], bh[8][2], bl[8][2];
#pragma unroll
            for (int mf = 0; mf < 2; mf++) {
                uint32_t ad = sAhi + ((rA + mf * 16) * STR + k0 + cOff) * 2;
                LDSM_X4(ah[mf][0], ah[mf][1], ah[mf][2], ah[mf][3], ad);
                uint32_t ad2 = sAlo + ((rA + mf * 16) * STR + k0 + cOff) * 2;
                LDSM_X4(al[mf][0], al[mf][1], al[mf][2], al[mf][3], ad2);
            }
#pragma unroll
            for (int q = 0; q < 4; q++) {
                uint32_t t0, t1, t2, t3;
                uint32_t bd = sBhi + ((rB + q * 16) * STR + k0 + cOff) * 2;
                LDSM_X4(t0, t1, t2, t3, bd);
                bh[2 * q][0] = t0; bh[2 * q + 1][0] = t1;
                bh[2 * q][1] = t2; bh[2 * q + 1][1] = t3;
                uint32_t bd2 = sBlo + ((rB + q * 16) * STR + k0 + cOff) * 2;
                LDSM_X4(t0, t1, t2, t3, bd2);
                bl[2 * q][0] = t0; bl[2 * q + 1][0] = t1;
                bl[2 * q][1] = t2; bl[2 * q + 1][1] = t3;
            }
#pragma unroll
            for (int mf = 0; mf < 2; mf++)
#pragma unroll
                for (int nf = 0; nf < 8; nf++) {
                    MMA_BF16(acc[mf][nf], ah[mf], bh[nf]);
                    MMA_BF16(acc[mf][nf], ah[mf], bl[nf]);
                    MMA_BF16(acc[mf][nf], al[mf], bh[nf]);
                }
        }
        __syncthreads();
    }

    // ---- epilogue: bias + relu + store ----
#pragma unroll
    for (int mf = 0; mf < 2; mf++) {
        int r1 = row0 + m0 + mf * 16 + gq;
        int r2 = r1 + 8;
#pragma unroll
        for (int nf = 0; nf < 8; nf++) {
            int c = n0 + nf * 8 + 2 * tq;
            float v0 = acc[mf][nf][0] + s_bias[c];
            float v1 = acc[mf][nf][1] + s_bias[c + 1];
            float v2 = acc[mf][nf][2] + s_bias[c];
            float v3 = acc[mf][nf][3] + s_bias[c + 1];
            if (do_relu) {
                v0 = fmaxf(v0, 0.f); v1 = fmaxf(v1, 0.f);
                v2 = fmaxf(v2, 0.f); v3 = fmaxf(v3, 0.f);
            }
            if (r1 < NN) { float2 o = {v0, v1}; *(float2*)(out + (size_t)r1 * DD + c) = o; }
            if (r2 < NN) { float2 o = {v2, v3}; *(float2*)(out + (size_t)r2 * DD + c) = o; }
        }
    }
}

// ---------------------------------------------------------------
// predictor via mma.sync (split-bf16, 3-term) — unchanged from R5
// ---------------------------------------------------------------
__global__ void __launch_bounds__(256) predictor_mma_kernel(
    const float* __restrict__ h,
    const int* __restrict__ pos_src, const int* __restrict__ pos_dst,
    const int* __restrict__ neg_src, const int* __restrict__ neg_dst,
    const float* __restrict__ bp1, const float* __restrict__ bp2,
    const float* __restrict__ Wp3, const float* __restrict__ bp3,
    float* __restrict__ out)
{
    extern __shared__ __nv_bfloat16 bsm[];
    __nv_bfloat16* Ahi = bsm;
    __nv_bfloat16* Alo = bsm + 128 * STR;
    __nv_bfloat16* Bhi = bsm + 2 * 128 * STR;
    __nv_bfloat16* Blo = bsm + 3 * 128 * STR;
    __shared__ float s_b1[DD], s_b2[DD], s_w3[DD];
    __shared__ float s_part[DD][2];

    int tid = threadIdx.x;
    int lane = tid & 31;
    int wid = tid >> 5;
    int wm = wid >> 1, wn = wid & 1;
    int m0 = wm * 32, n0 = wn * 64;
    int g0 = blockIdx.x * 128;

    if (tid < DD) {
        s_b1[tid] = bp1[tid];
        s_b2[tid] = bp2[tid];
        s_w3[tid] = Wp3[tid];
    }

    // ---- stage 1: A = split(h[s]*h[d]), B = split(W1^T) ----
    {
        int p = tid >> 1;
        int half = tid & 1;
        int g = g0 + p;
        int gm = g < 2 * PP ? g : 2 * PP - 1;
        int s, d;
        if (gm < PP) { s = pos_src[gm]; d = pos_dst[gm]; }
        else         { s = neg_src[gm - PP]; d = neg_dst[gm - PP]; }
        const float4* hs = (const float4*)(h + (size_t)s * DD + half * 64);
        const float4* hd = (const float4*)(h + (size_t)d * DD + half * 64);
#pragma unroll
        for (int i = 0; i < 16; i++) {
            float4 a = hs[i];
            float4 bv = hd[i];
            float e0 = a.x * bv.x, e1 = a.y * bv.y, e2 = a.z * bv.z, e3 = a.w * bv.w;
            uint32_t h01, l01, h23, l23;
            split2(e0, e1, h01, l01);
            split2(e2, e3, h23, l23);
            int k = half * 64 + i * 4;
            uint2 vh = {h01, h23};
            uint2 vl = {l01, l23};
            *(uint2*)&Ahi[p * STR + k] = vh;
            *(uint2*)&Alo[p * STR + k] = vl;
        }
        int n = tid >> 1;
        const uint2* w1h = (const uint2*)g_w1hi + n * 32 + half * 16;
        const uint2* w1l = (const uint2*)g_w1lo + n * 32 + half * 16;
#pragma unroll
        for (int i = 0; i < 16; i++) {
            int k = half * 64 + i * 4;
            *(uint2*)&Bhi[n * STR + k] = w1h[i];
            *(uint2*)&Blo[n * STR + k] = w1l[i];
        }
    }
    __syncthreads();

    uint32_t sAhi = smem_to_u32(Ahi), sAlo = smem_to_u32(Alo);
    uint32_t sBhi = smem_to_u32(Bhi), sBlo = smem_to_u32(Blo);
    int rA = m0 + (lane & 15);
    int rB = n0 + (lane & 15);
    int cOff = (lane >> 4) * 8;
    int gq = lane >> 2, tq = lane & 3;

    float acc[2][8][4];

    // ================= GEMM 1 =================
#pragma unroll
    for (int mf = 0; mf < 2; mf++)
#pragma unroll
        for (int nf = 0; nf < 8; nf++)
#pragma unroll
            for (int j = 0; j < 4; j++) acc[mf][nf][j] = 0.f;

#pragma unroll
    for (int ks = 0; ks < 8; ks++) {
        int k0 = ks * 16;
        uint32_t ah[2][4], al[2][4], bh[8][2], bl[8][2];
#pragma unroll
        for (int mf = 0; mf < 2; mf++) {
            uint32_t ad = sAhi + ((rA + mf * 16) * STR + k0 + cOff) * 2;
            LDSM_X4(ah[mf][0], ah[mf][1], ah[mf][2], ah[mf][3], ad);
            uint32_t ad2 = sAlo + ((rA + mf * 16) * STR + k0 + cOff) * 2;
            LDSM_X4(al[mf][0], al[mf][1], al[mf][2], al[mf][3], ad2);
        }
#pragma unroll
        for (int q = 0; q < 4; q++) {
            uint32_t bd = sBhi + ((rB + q * 16) * STR + k0 + cOff) * 2;
            uint32_t t0, t1, t2, t3;
            LDSM_X4(t0, t1, t2, t3, bd);
            bh[2 * q][0] = t0; bh[2 * q + 1][0] = t1;
            bh[2 * q][1] = t2; bh[2 * q + 1][1] = t3;
            uint32_t bd2 = sBlo + ((rB + q * 16) * STR + k0 + cOff) * 2;
            LDSM_X4(t0, t1, t2, t3, bd2);
            bl[2 * q][0] = t0; bl[2 * q + 1][0] = t1;
            bl[2 * q][1] = t2; bl[2 * q + 1][1] = t3;
        }
#pragma unroll
        for (int mf = 0; mf < 2; mf++)
#pragma unroll
            for (int nf = 0; nf < 8; nf++) {
                MMA_BF16(acc[mf][nf], ah[mf], bh[nf]);
                MMA_BF16(acc[mf][nf], ah[mf], bl[nf]);
                MMA_BF16(acc[mf][nf], al[mf], bh[nf]);
            }
    }
    __syncthreads();

    // ---- epilogue1: t1 = relu(D + bp1) split back into A tiles; load W2 ----
#pragma unroll
    for (int mf = 0; mf < 2; mf++) {
        int r1 = m0 + mf * 16 + gq;
        int r2 = r1 + 8;
#pragma unroll
        for (int nf = 0; nf < 8; nf++) {
            int c = n0 + nf * 8 + 2 * tq;
            float v0 = fmaxf(acc[mf][nf][0] + s_b1[c], 0.f);
            float v1 = fmaxf(acc[mf][nf][1] + s_b1[c + 1], 0.f);
            float v2 = fmaxf(acc[mf][nf][2] + s_b1[c], 0.f);
            float v3 = fmaxf(acc[mf][nf][3] + s_b1[c + 1], 0.f);
            uint32_t hh, ll;
            split2(v0, v1, hh, ll);
            *(uint32_t*)&Ahi[r1 * STR + c] = hh;
            *(uint32_t*)&Alo[r1 * STR + c] = ll;
            split2(v2, v3, hh, ll);
            *(uint32_t*)&Ahi[r2 * STR + c] = hh;
            *(uint32_t*)&Alo[r2 * STR + c] = ll;
        }
    }
    {
        int n = tid >> 1;
        int half = tid & 1;
        const uint2* w2h = (const uint2*)g_w2hi + n * 32 + half * 16;
        const uint2* w2l = (const uint2*)g_w2lo + n * 32 + half * 16;
#pragma unroll
        for (int i = 0; i < 16; i++) {
            int k = half * 64 + i * 4;
            *(uint2*)&Bhi[n * STR + k] = w2h[i];
            *(uint2*)&Blo[n * STR + k] = w2l[i];
        }
    }
    __syncthreads();

    // ================= GEMM 2 =================
#pragma unroll
    for (int mf = 0; mf < 2; mf++)
#pragma unroll
        for (int nf = 0; nf < 8; nf++)
#pragma unroll
            for (int j = 0; j < 4; j++) acc[mf][nf][j] = 0.f;

#pragma unroll
    for (int ks = 0; ks < 8; ks++) {
        int k0 = ks * 16;
        uint32_t ah[2][4], al[2][4], bh[8][2], bl[8][2];
#pragma unroll
        for (int mf = 0; mf < 2; mf++) {
            uint32_t ad = sAhi + ((rA + mf * 16) * STR + k0 + cOff) * 2;
            LDSM_X4(ah[mf][0], ah[mf][1], ah[mf][2], ah[mf][3], ad);
            uint32_t ad2 = sAlo + ((rA + mf * 16) * STR + k0 + cOff) * 2;
            LDSM_X4(al[mf][0], al[mf][1], al[mf][2], al[mf][3], ad2);
        }
#pragma unroll
        for (int q = 0; q < 4; q++) {
            uint32_t bd = sBhi + ((rB + q * 16) * STR + k0 + cOff) * 2;
            uint32_t t0, t1, t2, t3;
            LDSM_X4(t0, t1, t2, t3, bd);
            bh[2 * q][0] = t0; bh[2 * q + 1][0] = t1;
            bh[2 * q][1] = t2; bh[2 * q + 1][1] = t3;
            uint32_t bd2 = sBlo + ((rB + q * 16) * STR + k0 + cOff) * 2;
            LDSM_X4(t0, t1, t2, t3, bd2);
            bl[2 * q][0] = t0; bl[2 * q + 1][0] = t1;
            bl[2 * q][1] = t2; bl[2 * q + 1][1] = t3;
        }
#pragma unroll
        for (int mf = 0; mf < 2; mf++)
#pragma unroll
            for (int nf = 0; nf < 8; nf++) {
                MMA_BF16(acc[mf][nf], ah[mf], bh[nf]);
                MMA_BF16(acc[mf][nf], ah[mf], bl[nf]);
                MMA_BF16(acc[mf][nf], al[mf], bh[nf]);
            }
    }

    // ---- epilogue2: score = relu(D + bp2) . w3 (+bp3) ----
#pragma unroll
    for (int mf = 0; mf < 2; mf++) {
        float p0 = 0.f, p1 = 0.f;
#pragma unroll
        for (int nf = 0; nf < 8; nf++) {
            int c = n0 + nf * 8 + 2 * tq;
            p0 += fmaxf(acc[mf][nf][0] + s_b2[c], 0.f) * s_w3[c]
                + fmaxf(acc[mf][nf][1] + s_b2[c + 1], 0.f) * s_w3[c + 1];
            p1 += fmaxf(acc[mf][nf][2] + s_b2[c], 0.f) * s_w3[c]
                + fmaxf(acc[mf][nf][3] + s_b2[c + 1], 0.f) * s_w3[c + 1];
        }
        p0 += __shfl_xor_sync(0xffffffffu, p0, 1);
        p0 += __shfl_xor_sync(0xffffffffu, p0, 2);
        p1 += __shfl_xor_sync(0xffffffffu, p1, 1);
        p1 += __shfl_xor_sync(0xffffffffu, p1, 2);
        if (tq == 0) {
            s_part[m0 + mf * 16 + gq][wn] = p0;
            s_part[m0 + mf * 16 + gq + 8][wn] = p1;
        }
    }
    __syncthreads();
    if (tid < 128) {
        int g = g0 + tid;
        if (g < 2 * PP) out[g] = s_part[tid][0] + s_part[tid][1] + bp3[0];
    }
}

// ---------------------------------------------------------------
// launch
// ---------------------------------------------------------------
extern "C" void kernel_launch(void* const* d_in, const int* in_sizes, int n_in,
                              void* d_out, int out_size) {
    const float* x       = (const float*)d_in[0];
    const float* W_self  = (const float*)d_in[1];
    const float* W_neigh = (const float*)d_in[2];
    const float* b       = (const float*)d_in[3];
    const float* Wp1     = (const float*)d_in[4];
    const float* bp1     = (const float*)d_in[5];
    const float* Wp2     = (const float*)d_in[6];
    const float* bp2     = (const float*)d_in[7];
    const float* Wp3     = (const float*)d_in[8];
    const float* bp3     = (const float*)d_in[9];
    const int* edge_src  = (const int*)d_in[10];
    const int* edge_dst  = (const int*)d_in[11];
    const int* pos_src   = (const int*)d_in[12];
    const int* pos_dst   = (const int*)d_in[13];
    const int* neg_src   = (const int*)d_in[14];
    const int* neg_dst   = (const int*)d_in[15];
    float* out = (float*)d_out;

    float *hA, *hB, *agg;
    cudaGetSymbolAddress((void**)&hA, g_hA);
    cudaGetSymbolAddress((void**)&hB, g_hB);
    cudaGetSymbolAddress((void**)&agg, g_agg);

    static int attr_done = 0;
    const int TILE_SMEM = 4 * 128 * STR * 2;   // 139264
    if (!attr_done) {
        cudaFuncSetAttribute(predictor_mma_kernel,
                             cudaFuncAttributeMaxDynamicSharedMemorySize, TILE_SMEM);
        cudaFuncSetAttribute(sage_mma_kernel,
                             cudaFuncAttributeMaxDynamicSharedMemorySize, TILE_SMEM);
        attr_done = 1;
    }

    // ---- CSR build + weight prep ----
    deg_count_kernel<<<(EE + 255) / 256, 256>>>(edge_dst);
    prep_w_kernel<<<(3 * DD * DD + 255) / 256, 256>>>(W_self, W_neigh, Wp1, Wp2);
    const int NB = (NN + 1023) / 1024;
    scan1_kernel<<<NB, 1024>>>();
    scan2_kernel<<<1, 32>>>(NB);
    scan3_kernel<<<(NN + 255) / 256, 256>>>();
    fill_kernel<<<(EE + 255) / 256, 256>>>(edge_src, edge_dst);

    // ---- layers ----
    const float* hin = x;
    float* outs[3] = {hA, hB, hA};
    for (int l = 0; l < 3; l++) {
        aggregate_kernel<<<(NN * 32 + 255) / 256, 256>>>(hin, agg);
        sage_mma_kernel<<<(NN + 127) / 128, 256, TILE_SMEM>>>(
            hin, agg, b + (size_t)l * DD, outs[l], (l < 2) ? 1 : 0, l);
        hin = outs[l];
    }

    // ---- predictor ----
    predictor_mma_kernel<<<(2 * PP + 127) / 128, 256, TILE_SMEM>>>(
        hin, pos_src, pos_dst, neg_src, neg_dst,
        bp1, bp2, Wp3, bp3, out);
}